// round 12
// baseline (speedup 1.0000x reference)
#include <cuda_runtime.h>
#include <cstdio>
#include <cstdint>

#define BB 4
#define NSS 96
#define TT 8
#define HD 256
#define H4 1024
#define NW 1280
#define NN 97
#define NLAY 6
#define ROWS (BB*NN)     // 388
#define SEQS (BB*NSS)    // 384
#define TOK  (SEQS*TT)   // 3072

// ---------------- scratch -----------------------------------------------------
__device__ float g_xw[TOK*H4];         // token proj, GATE-INTERLEAVED [row][hh*4+g]
__device__ float g_Wt[HD*H4];          // Wh_s gate-interleaved [k][hh*4+g]
__device__ float g_Wxt[HD*H4];         // Wx_s gate-interleaved
__device__ float g_bst[H4];            // b_s gate-interleaved
__device__ float g_B1[HD*NW];          // [Wh_e | W_hk]
__device__ float g_B2[HD*NW];          // [Wx_e | W_sd]
__device__ float g_c0[SEQS*HD];
__device__ float g_hA[SEQS*HD];
__device__ float g_hB[SEQS*HD];
__device__ float g_pref[ROWS*HD];
__device__ float g_MeMs[HD*NW];
__device__ float g_pmS[ROWS*NW];       // cols 0-1023 = pm4, 1024+ = prS
__device__ float g_be[H4];
__device__ float g_bs[HD];
__device__ float g_S2[BB*NN*NN];
__device__ float g_u[ROWS*H4];
__device__ float g_hk[ROWS*HD];
__device__ float g_w[BB*NN*NN];
__device__ float g_cX[ROWS*HD], g_hX[ROWS*HD];
__device__ float g_cY[ROWS*HD], g_hY[ROWS*HD];
__device__ float g_pX[ROWS], g_pY[ROWS];
__device__ unsigned g_barL;            // lstm grid-barrier counter

// exp-based gates (statement LSTM path)
__device__ __forceinline__ float sigf(float x) {
    return __fdividef(1.0f, 1.0f + __expf(-x));
}
__device__ __forceinline__ float tanhr(float x) {
    return 2.0f * __fdividef(1.0f, 1.0f + __expf(-2.0f * x)) - 1.0f;
}
// HW-tanh gates (agg hot loop)
__device__ __forceinline__ float tanhw(float x) {
    float y;
    asm("tanh.approx.f32 %0, %1;" : "=f"(y) : "f"(x));
    return y;
}
__device__ __forceinline__ float sigw(float x) {
    return fmaf(0.5f, tanhw(0.5f * x), 0.5f);
}

__device__ __forceinline__ float to_tf32(float x) {
    uint32_t o;
    asm("cvt.rna.tf32.f32 %0, %1;" : "=r"(o) : "f"(x));
    return __uint_as_float(o);
}

__device__ __forceinline__ void mma_tf32(float& c0, float& c1, float& c2, float& c3,
                                         float a0, float a1, float a2, float a3,
                                         float b0, float b1) {
    asm volatile(
        "mma.sync.aligned.m16n8k8.row.col.f32.tf32.tf32.f32 "
        "{%0,%1,%2,%3},{%4,%5,%6,%7},{%8,%9},{%0,%1,%2,%3};"
        : "+f"(c0), "+f"(c1), "+f"(c2), "+f"(c3)
        : "r"(__float_as_uint(a0)), "r"(__float_as_uint(a1)),
          "r"(__float_as_uint(a2)), "r"(__float_as_uint(a3)),
          "r"(__float_as_uint(b0)), "r"(__float_as_uint(b1)));
}

// generation-based grid barrier (all blocks must call; counter zeroed in prep)
__device__ __forceinline__ void grid_bar(unsigned* ctr, unsigned* gen, unsigned nb) {
    __syncthreads();
    if (threadIdx.x == 0) {
        *gen += nb;
        unsigned target = *gen;
        __threadfence();
        atomicAdd(ctr, 1u);
        while (*(volatile unsigned*)ctr < target) __nanosleep(64);
        __threadfence();
    }
    __syncthreads();
}

// ---------------- tf32 MMA GEMM, K=256, tile 64x64, double-buffered -----------
// EPI: 0 = plain (+opt bias), 2 = u + hk
#define SA_STRIDE 36
#define SB_STRIDE 72
#define BUF_STRIDE 68
#define TILE_FLOATS (64*SA_STRIDE + 32*SB_STRIDE)   // 4608
template<int EPI>
__global__ __launch_bounds__(256)
void mma_gemm(const float* __restrict__ A, const int* __restrict__ gidx,
              const float* __restrict__ B, const float* __restrict__ bias,
              float* __restrict__ C, int M, int N,
              const float* __restrict__ be, const float* __restrict__ pmS,
              const float* __restrict__ b_hk, const float* __restrict__ W_d1,
              float* __restrict__ u, float* __restrict__ hkbuf) {
    __shared__ float smem[2 * TILE_FLOATS];
    const int tid = threadIdx.x;
    const int lane = tid & 31, warp = tid >> 5;
    const int wm = warp >> 1, wn = warp & 1;     // 4x2 warp grid
    const int g = lane >> 2, tg = lane & 3;
    const int bm = blockIdx.x * 64, bn = blockIdx.y * 64;

    const int ar_r  = tid >> 3;
    const int ar_kc = (tid & 7) << 2;
    const int br_kk = tid >> 4;
    const int br_c  = (tid & 15) << 2;

    float4 va[2], vb[2];
    auto load_regs = [&](int k0) {
#pragma unroll
        for (int l = 0; l < 2; l++) {
            int r = ar_r + l * 32;
            int row = bm + r;
            float4 v = make_float4(0.f, 0.f, 0.f, 0.f);
            if (row < M) {
                int ar = gidx ? gidx[row] : row;
                v = *(const float4*)(A + (size_t)ar * HD + k0 + ar_kc);
            }
            va[l] = v;
        }
#pragma unroll
        for (int l = 0; l < 2; l++) {
            int kk = br_kk + l * 16;
            vb[l] = *(const float4*)(B + (size_t)(k0 + kk) * N + bn + br_c);
        }
    };
    auto store_smem = [&](int buf) {
        float* sA = smem + buf * TILE_FLOATS;
        float* sB = sA + 64 * SA_STRIDE;
#pragma unroll
        for (int l = 0; l < 2; l++) {
            float* d = sA + (ar_r + l * 32) * SA_STRIDE + ar_kc;
            d[0] = to_tf32(va[l].x); d[1] = to_tf32(va[l].y);
            d[2] = to_tf32(va[l].z); d[3] = to_tf32(va[l].w);
        }
#pragma unroll
        for (int l = 0; l < 2; l++) {
            float* d = sB + (br_kk + l * 16) * SB_STRIDE + br_c;
            d[0] = to_tf32(vb[l].x); d[1] = to_tf32(vb[l].y);
            d[2] = to_tf32(vb[l].z); d[3] = to_tf32(vb[l].w);
        }
    };

    float acc[4][4];
#pragma unroll
    for (int a = 0; a < 4; a++)
#pragma unroll
        for (int b = 0; b < 4; b++) acc[a][b] = 0.f;

    load_regs(0);
    store_smem(0);
    __syncthreads();

    constexpr int NT = HD / 32;
#pragma unroll
    for (int it = 0; it < NT; it++) {
        if (it + 1 < NT) load_regs((it + 1) * 32);
        const float* sA = smem + (it & 1) * TILE_FLOATS;
        const float* sB = sA + 64 * SA_STRIDE;
#pragma unroll
        for (int k8 = 0; k8 < 4; k8++) {
            int kb = k8 * 8;
            float a0 = sA[(wm * 16 + g) * SA_STRIDE + kb + tg];
            float a1 = sA[(wm * 16 + g + 8) * SA_STRIDE + kb + tg];
            float a2 = sA[(wm * 16 + g) * SA_STRIDE + kb + tg + 4];
            float a3 = sA[(wm * 16 + g + 8) * SA_STRIDE + kb + tg + 4];
#pragma unroll
            for (int nt = 0; nt < 4; nt++) {
                int nc = wn * 32 + nt * 8 + g;
                float b0 = sB[(kb + tg) * SB_STRIDE + nc];
                float b1 = sB[(kb + tg + 4) * SB_STRIDE + nc];
                mma_tf32(acc[nt][0], acc[nt][1], acc[nt][2], acc[nt][3],
                         a0, a1, a2, a3, b0, b1);
            }
        }
        if (it + 1 < NT) {
            store_smem((it + 1) & 1);
            __syncthreads();
        }
    }

#pragma unroll
    for (int nt = 0; nt < 4; nt++)
#pragma unroll
        for (int e = 0; e < 4; e++) {
            int row = bm + wm * 16 + g + ((e >> 1) ? 8 : 0);
            int col = bn + wn * 32 + nt * 8 + tg * 2 + (e & 1);
            if (row >= M) continue;
            float v = acc[nt][e];
            if (EPI == 0) {
                C[(size_t)row * N + col] = v + (bias ? bias[col] : 0.f);
            } else {  // EPI == 2
                if (col < H4) {
                    u[(size_t)row * H4 + col] = v + be[col] - pmS[(size_t)row * NW + col];
                } else {
                    int cc = col - H4;
                    hkbuf[(size_t)row * HD + cc] =
                        fmaxf(v + b_hk[cc], 0.f) * W_d1[cc];
                }
            }
        }
}

// ---------------- persistent statement LSTM (grid = 96, Wt resident in smem) --
// smem: sW = 8 chunks x [32][72] (73728B), sA = 8 chunks x [64][36] (73728B)
#define LSTM_SMEM_BYTES (2 * 18432 * 4)
__global__ __launch_bounds__(256)
void lstm_persist_kernel(const float* __restrict__ xw, const float* __restrict__ Wt,
                         float* __restrict__ c0, float* __restrict__ hA,
                         float* __restrict__ hB) {
    extern __shared__ float dyn[];
    float* sW = dyn;
    float* sA = dyn + 18432;
    unsigned gen = 0;
    const int tid = threadIdx.x;
    const int lane = tid & 31, warp = tid >> 5;
    const int wm = warp >> 1, wn = warp & 1;
    const int g = lane >> 2, tg = lane & 3;
    const int bm = (blockIdx.x % 6) * 64;
    const int bn = (blockIdx.x / 6) * 64;
    const int ar_r = tid >> 3, ar_kc = (tid & 7) << 2;
    const int br_kk = tid >> 4, br_c = (tid & 15) << 2;

    // load Wt slice ONCE (tf32-converted)
#pragma unroll
    for (int ch = 0; ch < 8; ch++) {
        int k0 = ch * 32;
        float* sWc = sW + ch * (32 * SB_STRIDE);
#pragma unroll
        for (int l = 0; l < 2; l++) {
            int kk = br_kk + l * 16;
            float4 v = *(const float4*)(Wt + (size_t)(k0 + kk) * H4 + bn + br_c);
            float* d = sWc + kk * SB_STRIDE + br_c;
            d[0] = to_tf32(v.x); d[1] = to_tf32(v.y);
            d[2] = to_tf32(v.z); d[3] = to_tf32(v.w);
        }
    }

    // gate0 for own (row-tile, hh-tile) portion: z = xw[t=0], c_prev = 0
#pragma unroll
    for (int l = 0; l < 4; l++) {
        int pi = tid + l * 256;
        int lr = pi & 63, lh = pi >> 6;
        int row = bm + lr, hh = (bn >> 2) + lh;
        float4 x4 = *(const float4*)(xw + (size_t)row * (TT * H4) + hh * 4);
        float c2 = sigf(x4.x) * tanhr(x4.z);
        size_t idx = (size_t)row * HD + hh;
        c0[idx] = c2;
        hA[idx] = sigf(x4.w) * tanhr(c2);
    }
    grid_bar(&g_barL, &gen, gridDim.x);

    const float* hs = hA;
    float* hd = hB;
    for (int t = 1; t < TT; t++) {
        // load A (= current h) tile, L2-coherent
#pragma unroll
        for (int ch = 0; ch < 8; ch++) {
            int k0 = ch * 32;
            float* sAc = sA + ch * (64 * SA_STRIDE);
#pragma unroll
            for (int l = 0; l < 2; l++) {
                int r = ar_r + l * 32;
                float4 v = __ldcg((const float4*)(hs + (size_t)(bm + r) * HD + k0 + ar_kc));
                float* d = sAc + r * SA_STRIDE + ar_kc;
                d[0] = to_tf32(v.x); d[1] = to_tf32(v.y);
                d[2] = to_tf32(v.z); d[3] = to_tf32(v.w);
            }
        }
        __syncthreads();

        float acc[4][4];
#pragma unroll
        for (int a = 0; a < 4; a++)
#pragma unroll
            for (int b = 0; b < 4; b++) acc[a][b] = 0.f;
#pragma unroll
        for (int it = 0; it < 8; it++) {
            const float* sAc = sA + it * (64 * SA_STRIDE);
            const float* sWc = sW + it * (32 * SB_STRIDE);
#pragma unroll
            for (int k8 = 0; k8 < 4; k8++) {
                int kb = k8 * 8;
                float a0 = sAc[(wm * 16 + g) * SA_STRIDE + kb + tg];
                float a1 = sAc[(wm * 16 + g + 8) * SA_STRIDE + kb + tg];
                float a2 = sAc[(wm * 16 + g) * SA_STRIDE + kb + tg + 4];
                float a3 = sAc[(wm * 16 + g + 8) * SA_STRIDE + kb + tg + 4];
#pragma unroll
                for (int nt = 0; nt < 4; nt++) {
                    int nc = wn * 32 + nt * 8 + g;
                    float b0 = sWc[(kb + tg) * SB_STRIDE + nc];
                    float b1 = sWc[(kb + tg + 4) * SB_STRIDE + nc];
                    mma_tf32(acc[nt][0], acc[nt][1], acc[nt][2], acc[nt][3],
                             a0, a1, a2, a3, b0, b1);
                }
            }
        }
        __syncthreads();

        // stage accumulators into sA region, regroup gates, apply LSTM
        float* buf = sA;
#pragma unroll
        for (int nt = 0; nt < 4; nt++)
#pragma unroll
            for (int e = 0; e < 4; e++) {
                int lr = wm * 16 + g + ((e >> 1) ? 8 : 0);
                int lc = wn * 32 + nt * 8 + tg * 2 + (e & 1);
                buf[lr * BUF_STRIDE + lc] = acc[nt][e];
            }
        __syncthreads();
#pragma unroll
        for (int l = 0; l < 4; l++) {
            int pi = tid + l * 256;
            int lr = pi & 63, lh = pi >> 6;
            int row = bm + lr, hh = (bn >> 2) + lh;
            float4 z4 = *(const float4*)(buf + lr * BUF_STRIDE + lh * 4);
            float4 x4 = *(const float4*)(xw + (size_t)row * (TT * H4) + t * H4 + hh * 4);
            float zi = z4.x + x4.x;
            float zf = z4.y + x4.y;
            float zg = z4.z + x4.z;
            float zo = z4.w + x4.w;
            size_t idx = (size_t)row * HD + hh;
            float cp = c0[idx];
            float c2 = sigf(zf) * cp + sigf(zi) * tanhr(zg);
            c0[idx] = c2;
            hd[idx] = sigf(zo) * tanhr(c2);
        }
        grid_bar(&g_barL, &gen, gridDim.x);
        const float* tmp = hs; hs = hd; hd = (float*)tmp;
    }
}

// ---------------- merged prep: Wt, Wxt, bst, B1, B2, be, bs (+bar reset) ------
__global__ void prep_kernel(const float* __restrict__ Wh_s, const float* __restrict__ Wx_s,
                            const float* __restrict__ b_s,
                            const float* __restrict__ Wh_e, const float* __restrict__ W_hk,
                            const float* __restrict__ Wx_e, const float* __restrict__ W_sd,
                            const float* __restrict__ b_se, const float* __restrict__ b_e,
                            const float* __restrict__ b_sd,
                            float* __restrict__ Wt, float* __restrict__ Wxt,
                            float* __restrict__ bst,
                            float* __restrict__ B1, float* __restrict__ B2,
                            float* __restrict__ be, float* __restrict__ bs) {
    int idx = blockIdx.x * 256 + threadIdx.x;
    if (idx == 0) g_barL = 0u;
    if (idx < HD * H4) {
        int k = idx / H4, col = idx % H4;
        int g = col / HD, hh = col % HD;
        Wt[(size_t)k * H4 + hh * 4 + g] = Wh_s[idx];
        Wxt[(size_t)k * H4 + hh * 4 + g] = Wx_s[idx];
    }
    if (idx < H4) {
        int g = idx / HD, hh = idx % HD;
        bst[hh * 4 + g] = b_s[idx];
    }
    if (idx < HD * NW) {
        int k = idx / NW, c = idx % NW;
        B1[idx] = (c < H4) ? Wh_e[(size_t)k * H4 + c] : W_hk[(size_t)k * HD + (c - H4)];
        B2[idx] = (c < H4) ? Wx_e[(size_t)k * H4 + c] : W_sd[(size_t)k * HD + (c - H4)];
    }
    if (idx < H4) {
        float acc = b_e[idx];
        for (int k = 0; k < HD; k++) acc += b_se[k] * Wx_e[(size_t)k * H4 + idx];
        be[idx] = acc;
    } else if (idx < H4 + HD) {
        int c = idx - H4;
        float acc = b_sd[c];
        for (int k = 0; k < HD; k++) acc += b_se[k] * W_sd[(size_t)k * HD + c];
        bs[c] = acc;
    }
}

__global__ void cumsum_kernel(const float* __restrict__ stmt, float* __restrict__ pref) {
    int b = blockIdx.x, hh = threadIdx.x;
    float acc = 0.f;
    pref[(size_t)(b * NN) * HD + hh] = 0.f;
    for (int k = 1; k < NN; k++) {
        acc += stmt[(size_t)(b * NSS + k - 1) * HD + hh];
        pref[(size_t)(b * NN + k) * HD + hh] = acc;
    }
}

// S2 + exec-state init merged (grid = ROWS, 128 threads)
__global__ void s2_init_kernel(const float* __restrict__ pmS, const float* __restrict__ bs,
                               const float* __restrict__ W_d1, float* __restrict__ S2,
                               const float* __restrict__ ia, const float* __restrict__ ib,
                               float* __restrict__ cX, float* __restrict__ hX,
                               float* __restrict__ pX) {
    int bi = blockIdx.x;
    int b = bi / NN;
    int lane = threadIdx.x & 31, warp = threadIdx.x >> 5;
    for (int hh = threadIdx.x; hh < HD; hh += 128) {
        cX[(size_t)bi * HD + hh] = ia[hh];
        hX[(size_t)bi * HD + hh] = ib[hh];
    }
    if (threadIdx.x == 0) pX[bi] = (bi % NN == 0) ? 1.f : 0.f;
    const float* pi = pmS + (size_t)bi * NW + H4;
    for (int j = warp; j < NN; j += 4) {
        const float* pj = pmS + (size_t)(b * NN + j) * NW + H4;
        float acc = 0.f;
#pragma unroll
        for (int l = 0; l < 8; l++) {
            int hh = lane + l * 32;
            float v = pj[hh] - pi[hh] + bs[hh];
            acc += fmaxf(v, 0.f) * W_d1[HD + hh];
        }
        for (int o = 16; o; o >>= 1) acc += __shfl_xor_sync(0xFFFFFFFFu, acc, o);
        if (lane == 0) S2[(size_t)bi * NN + j] = acc;
    }
}

// ---------------- per-layer: softmax ------------------------------------------
__global__ void softmax_kernel(const float* __restrict__ hkbuf,
                               const float* __restrict__ S2, const float* __restrict__ b_d1,
                               const float* __restrict__ p, const int* __restrict__ clen,
                               int layer, float* __restrict__ w) {
    int bi = blockIdx.x, b = bi / NN, i = bi % NN;
    int tid = threadIdx.x;   // 256
    __shared__ float red[256];
    red[tid] = hkbuf[(size_t)bi * HD + tid];
    __syncthreads();
    for (int s = 128; s > 0; s >>= 1) {
        if (tid < s) red[tid] += red[tid + s];
        __syncthreads();
    }
    float a = red[0];
    __syncthreads();

    int len = clen[b] / TT;
    int j = tid;
    bool m = false;
    if (j < NN) {
        if (layer == 0)             m = (j == 1);
        else if (layer == NLAY - 1) m = (j == len);
        else                        m = ((j > i) && (j <= len)) || (j == len);
    }
    float logit = m ? (a + S2[(size_t)bi * NN + j] + b_d1[0]) : -1e30f;
    red[tid] = logit; __syncthreads();
    for (int s = 128; s > 0; s >>= 1) {
        if (tid < s) red[tid] = fmaxf(red[tid], red[tid + s]);
        __syncthreads();
    }
    float mx = red[0]; __syncthreads();
    float e = m ? __expf(logit - mx) : 0.f;
    red[tid] = e; __syncthreads();
    for (int s = 128; s > 0; s >>= 1) {
        if (tid < s) red[tid] += red[tid + s];
        __syncthreads();
    }
    float sum = red[0];
    if (j < NN) w[(size_t)bi * NN + j] = p[bi] * __fdividef(e, sum);
}

// ---------------- per-layer: gated aggregation (HW tanh gates) ----------------
__global__ void agg_kernel(const float* __restrict__ w, const float* __restrict__ pmS,
                           const float* __restrict__ u,
                           const float* __restrict__ cIn, const float* __restrict__ hIn,
                           float* __restrict__ cOut, float* __restrict__ hOut,
                           float* __restrict__ pOut) {
    int bj = blockIdx.x, b = bj / NN, j = bj % NN;
    int hh = threadIdx.x;  // 256
    __shared__ float sw[NN];
    if (hh < NN) sw[hh] = w[((size_t)(b * NN + hh)) * NN + j];
    __syncthreads();
    const float* pj = pmS + (size_t)bj * NW;
    float zj0 = pj[hh], zj1 = pj[HD + hh], zj2 = pj[2 * HD + hh], zj3 = pj[3 * HD + hh];
    float accC = 0.f, accH = 0.f, wsum = 0.f;
    for (int i = 0; i < NN; i++) {
        float wi = sw[i];
        wsum += wi;
        if (wi == 0.f) continue;
        int ri = b * NN + i;
        float cp, hp;
        if (j > i) {
            const float* ui = u + (size_t)ri * H4;
            float zi = zj0 + ui[hh];
            float zf = zj1 + ui[HD + hh];
            float zg = zj2 + ui[2 * HD + hh];
            float zo = zj3 + ui[3 * HD + hh];
            float cold = cIn[(size_t)ri * HD + hh];
            cp = sigw(zf) * cold + sigw(zi) * tanhw(zg);
            hp = sigw(zo) * tanhw(cp);
        } else {
            cp = cIn[(size_t)ri * HD + hh];
            hp = hIn[(size_t)ri * HD + hh];
        }
        accC += wi * cp;
        accH += wi * hp;
    }
    float inv = __fdividef(1.f, wsum + 1e-7f);
    cOut[(size_t)bj * HD + hh] = accC * inv;
    hOut[(size_t)bj * HD + hh] = accH * inv;
    if (hh == 0) pOut[bj] = wsum;
}

// ------------------------------------------------------------------------------
static float* sym(const void* s) {
    void* p = nullptr;
    cudaGetSymbolAddress(&p, s);
    return (float*)p;
}

extern "C" void kernel_launch(void* const* d_in, const int* in_sizes, int n_in,
                              void* d_out, int out_size) {
    const int*   ids    = (const int*)d_in[0];
    const int*   clen   = (const int*)d_in[1];
    const float* embed  = (const float*)d_in[2];
    const float* Wx_s   = (const float*)d_in[3];
    const float* Wh_s   = (const float*)d_in[4];
    const float* b_s    = (const float*)d_in[5];
    const float* W_se   = (const float*)d_in[6];
    const float* b_se   = (const float*)d_in[7];
    const float* Wx_e   = (const float*)d_in[8];
    const float* Wh_e   = (const float*)d_in[9];
    const float* b_e    = (const float*)d_in[10];
    const float* W_hk   = (const float*)d_in[11];
    const float* b_hk   = (const float*)d_in[12];
    const float* W_sd   = (const float*)d_in[13];
    const float* b_sd   = (const float*)d_in[14];
    const float* W_d1   = (const float*)d_in[15];
    const float* b_d1   = (const float*)d_in[16];
    const float* init_a = (const float*)d_in[17];
    const float* init_b = (const float*)d_in[18];

    float* xw   = sym(g_xw);
    float* Wt   = sym(g_Wt);
    float* Wxt  = sym(g_Wxt);
    float* bst  = sym(g_bst);
    float* B1   = sym(g_B1);
    float* B2   = sym(g_B2);
    float* c0   = sym(g_c0);
    float* hA   = sym(g_hA);
    float* hB   = sym(g_hB);
    float* pref = sym(g_pref);
    float* MeMs = sym(g_MeMs);
    float* pmS  = sym(g_pmS);
    float* be   = sym(g_be);
    float* bs   = sym(g_bs);
    float* S2   = sym(g_S2);
    float* uBuf = sym(g_u);
    float* hk   = sym(g_hk);
    float* wM   = sym(g_w);
    float* cX   = sym(g_cX);
    float* hX   = sym(g_hX);
    float* cY   = sym(g_cY);
    float* hY   = sym(g_hY);
    float* pX   = sym(g_pX);
    float* pY   = sym(g_pY);

    cudaFuncSetAttribute(lstm_persist_kernel,
                         cudaFuncAttributeMaxDynamicSharedMemorySize, LSTM_SMEM_BYTES);

    // 0) merged prep (also resets barrier counter)
    prep_kernel<<<(HD * NW + 255) / 256, 256>>>(
        Wh_s, Wx_s, b_s, Wh_e, W_hk, Wx_e, W_sd, b_se, b_e, b_sd,
        Wt, Wxt, bst, B1, B2, be, bs);

    // 1) token projection (gate-interleaved output)
    mma_gemm<0><<<dim3(TOK / 64, H4 / 64), 256>>>(
        embed, ids, Wxt, bst, xw, TOK, H4,
        nullptr, nullptr, nullptr, nullptr, nullptr, nullptr);

    // 2) statement LSTM — ONE persistent kernel (final h lands in hB: TT-1=7 odd)
    lstm_persist_kernel<<<96, 256, LSTM_SMEM_BYTES>>>(xw, Wt, c0, hA, hB);

    // 3) prefix sums
    cumsum_kernel<<<BB, HD>>>(hB, pref);

    // 4) composed tables
    mma_gemm<0><<<dim3(HD / 64, NW / 64), 256>>>(
        W_se, nullptr, B2, nullptr, MeMs, HD, NW,
        nullptr, nullptr, nullptr, nullptr, nullptr, nullptr);
    mma_gemm<0><<<dim3((ROWS + 63) / 64, NW / 64), 256>>>(
        pref, nullptr, MeMs, nullptr, pmS, ROWS, NW,
        nullptr, nullptr, nullptr, nullptr, nullptr, nullptr);

    // 5) S2 + exec init merged
    s2_init_kernel<<<ROWS, 128>>>(pmS, bs, W_d1, S2, init_a, init_b, cX, hX, pX);

    // 6) execution layers
    float *cS = cX, *hS = hX, *pS = pX, *cD = cY, *hD2 = hY, *pD = pY;
    for (int layer = 0; layer < NLAY; layer++) {
        mma_gemm<2><<<dim3((ROWS + 63) / 64, NW / 64), 256>>>(
            hS, nullptr, B1, nullptr, nullptr, ROWS, NW,
            be, pmS, b_hk, W_d1, uBuf, hk);
        softmax_kernel<<<ROWS, 256>>>(hk, S2, b_d1, pS, clen, layer, wM);
        float* hOutPtr = (layer == NLAY - 1) ? (float*)d_out : hD2;
        agg_kernel<<<ROWS, 256>>>(wM, pmS, uBuf, cS, hS, cD, hOutPtr, pD);
        float* t;
        t = cS; cS = cD; cD = t;
        t = hS; hS = hD2; hD2 = t;
        t = pS; pS = pD; pD = t;
    }
}

// round 13
// speedup vs baseline: 1.0375x; 1.0375x over previous
#include <cuda_runtime.h>
#include <cstdio>
#include <cstdint>

#define BB 4
#define NSS 96
#define TT 8
#define HD 256
#define H4 1024
#define NW 1280
#define NN 97
#define NLAY 6
#define ROWS (BB*NN)     // 388
#define SEQS (BB*NSS)    // 384
#define TOK  (SEQS*TT)   // 3072

// ---------------- scratch -----------------------------------------------------
__device__ float g_xw[TOK*H4];         // token proj, GATE-INTERLEAVED [row][hh*4+g]
__device__ float g_Wt[HD*H4];          // Wh_s gate-interleaved [k][hh*4+g]
__device__ float g_Wxt[HD*H4];         // Wx_s gate-interleaved
__device__ float g_bst[H4];            // b_s gate-interleaved
__device__ float g_B1[HD*NW];          // [Wh_e | W_hk]
__device__ float g_B2[HD*NW];          // [Wx_e | W_sd]
__device__ float g_c0[SEQS*HD];
__device__ float g_hA[SEQS*HD];
__device__ float g_hB[SEQS*HD];
__device__ float g_pref[ROWS*HD];
__device__ float g_MeMs[HD*NW];
__device__ float g_pmS[ROWS*NW];       // cols 0-1023 = pm4, 1024+ = prS
__device__ float g_be[H4];
__device__ float g_bs[HD];
__device__ float g_uInit[H4];          // init_b@Wh_e + b_se@Wx_e + b_e
__device__ float g_S2[BB*NN*NN];
__device__ float g_u[ROWS*H4];
__device__ float g_hk[ROWS*HD];
__device__ float g_w[BB*NN*NN];
__device__ float g_cX[ROWS*HD], g_hX[ROWS*HD];
__device__ float g_cY[ROWS*HD], g_hY[ROWS*HD];
__device__ float g_pX[ROWS], g_pY[ROWS];
__device__ unsigned g_barL;            // lstm grid-barrier counter

// exp-based gates (statement LSTM / layer0 path)
__device__ __forceinline__ float sigf(float x) {
    return __fdividef(1.0f, 1.0f + __expf(-x));
}
__device__ __forceinline__ float tanhr(float x) {
    return 2.0f * __fdividef(1.0f, 1.0f + __expf(-2.0f * x)) - 1.0f;
}
// HW-tanh gates (agg hot loop)
__device__ __forceinline__ float tanhw(float x) {
    float y;
    asm("tanh.approx.f32 %0, %1;" : "=f"(y) : "f"(x));
    return y;
}
__device__ __forceinline__ float sigw(float x) {
    return fmaf(0.5f, tanhw(0.5f * x), 0.5f);
}

__device__ __forceinline__ float to_tf32(float x) {
    uint32_t o;
    asm("cvt.rna.tf32.f32 %0, %1;" : "=r"(o) : "f"(x));
    return __uint_as_float(o);
}

__device__ __forceinline__ void mma_tf32(float& c0, float& c1, float& c2, float& c3,
                                         float a0, float a1, float a2, float a3,
                                         float b0, float b1) {
    asm volatile(
        "mma.sync.aligned.m16n8k8.row.col.f32.tf32.tf32.f32 "
        "{%0,%1,%2,%3},{%4,%5,%6,%7},{%8,%9},{%0,%1,%2,%3};"
        : "+f"(c0), "+f"(c1), "+f"(c2), "+f"(c3)
        : "r"(__float_as_uint(a0)), "r"(__float_as_uint(a1)),
          "r"(__float_as_uint(a2)), "r"(__float_as_uint(a3)),
          "r"(__float_as_uint(b0)), "r"(__float_as_uint(b1)));
}

// generation-based grid barrier
__device__ __forceinline__ void grid_bar(unsigned* ctr, unsigned* gen, unsigned nb) {
    __syncthreads();
    if (threadIdx.x == 0) {
        *gen += nb;
        unsigned target = *gen;
        __threadfence();
        atomicAdd(ctr, 1u);
        while (*(volatile unsigned*)ctr < target) __nanosleep(64);
        __threadfence();
    }
    __syncthreads();
}

// ---------------- tf32 MMA GEMM, K=256, tile 64x64, double-buffered -----------
// EPI: 0 = plain (+opt bias), 2 = u + hk (with p-based tile skip)
#define SA_STRIDE 36
#define SB_STRIDE 72
#define BUF_STRIDE 68
#define TILE_FLOATS (64*SA_STRIDE + 32*SB_STRIDE)   // 4608
template<int EPI>
__global__ __launch_bounds__(256)
void mma_gemm(const float* __restrict__ A, const int* __restrict__ gidx,
              const float* __restrict__ B, const float* __restrict__ bias,
              float* __restrict__ C, int M, int N,
              const float* __restrict__ be, const float* __restrict__ pmS,
              const float* __restrict__ b_hk, const float* __restrict__ W_d1,
              float* __restrict__ u, float* __restrict__ hkbuf,
              const float* __restrict__ pcheck) {
    __shared__ float smem[2 * TILE_FLOATS];
    __shared__ int s_active;
    const int tid = threadIdx.x;
    const int lane = tid & 31, warp = tid >> 5;
    const int wm = warp >> 1, wn = warp & 1;
    const int g = lane >> 2, tg = lane & 3;
    const int bm = blockIdx.x * 64, bn = blockIdx.y * 64;

    if (EPI == 2) {
        if (tid == 0) s_active = 0;
        __syncthreads();
        if (tid < 64) {
            int row = bm + tid;
            if (row < M && pcheck[row] != 0.f) s_active = 1;
        }
        __syncthreads();
        if (!s_active) return;   // u/hk rows stale; unread because p==0 downstream
    }

    const int ar_r  = tid >> 3;
    const int ar_kc = (tid & 7) << 2;
    const int br_kk = tid >> 4;
    const int br_c  = (tid & 15) << 2;

    float4 va[2], vb[2];
    auto load_regs = [&](int k0) {
#pragma unroll
        for (int l = 0; l < 2; l++) {
            int r = ar_r + l * 32;
            int row = bm + r;
            float4 v = make_float4(0.f, 0.f, 0.f, 0.f);
            if (row < M) {
                int ar = gidx ? gidx[row] : row;
                v = *(const float4*)(A + (size_t)ar * HD + k0 + ar_kc);
            }
            va[l] = v;
        }
#pragma unroll
        for (int l = 0; l < 2; l++) {
            int kk = br_kk + l * 16;
            vb[l] = *(const float4*)(B + (size_t)(k0 + kk) * N + bn + br_c);
        }
    };
    auto store_smem = [&](int buf) {
        float* sA = smem + buf * TILE_FLOATS;
        float* sB = sA + 64 * SA_STRIDE;
#pragma unroll
        for (int l = 0; l < 2; l++) {
            float* d = sA + (ar_r + l * 32) * SA_STRIDE + ar_kc;
            d[0] = to_tf32(va[l].x); d[1] = to_tf32(va[l].y);
            d[2] = to_tf32(va[l].z); d[3] = to_tf32(va[l].w);
        }
#pragma unroll
        for (int l = 0; l < 2; l++) {
            float* d = sB + (br_kk + l * 16) * SB_STRIDE + br_c;
            d[0] = to_tf32(vb[l].x); d[1] = to_tf32(vb[l].y);
            d[2] = to_tf32(vb[l].z); d[3] = to_tf32(vb[l].w);
        }
    };

    float acc[4][4];
#pragma unroll
    for (int a = 0; a < 4; a++)
#pragma unroll
        for (int b = 0; b < 4; b++) acc[a][b] = 0.f;

    load_regs(0);
    store_smem(0);
    __syncthreads();

    constexpr int NT = HD / 32;
#pragma unroll
    for (int it = 0; it < NT; it++) {
        if (it + 1 < NT) load_regs((it + 1) * 32);
        const float* sA = smem + (it & 1) * TILE_FLOATS;
        const float* sB = sA + 64 * SA_STRIDE;
#pragma unroll
        for (int k8 = 0; k8 < 4; k8++) {
            int kb = k8 * 8;
            float a0 = sA[(wm * 16 + g) * SA_STRIDE + kb + tg];
            float a1 = sA[(wm * 16 + g + 8) * SA_STRIDE + kb + tg];
            float a2 = sA[(wm * 16 + g) * SA_STRIDE + kb + tg + 4];
            float a3 = sA[(wm * 16 + g + 8) * SA_STRIDE + kb + tg + 4];
#pragma unroll
            for (int nt = 0; nt < 4; nt++) {
                int nc = wn * 32 + nt * 8 + g;
                float b0 = sB[(kb + tg) * SB_STRIDE + nc];
                float b1 = sB[(kb + tg + 4) * SB_STRIDE + nc];
                mma_tf32(acc[nt][0], acc[nt][1], acc[nt][2], acc[nt][3],
                         a0, a1, a2, a3, b0, b1);
            }
        }
        if (it + 1 < NT) {
            store_smem((it + 1) & 1);
            __syncthreads();
        }
    }

#pragma unroll
    for (int nt = 0; nt < 4; nt++)
#pragma unroll
        for (int e = 0; e < 4; e++) {
            int row = bm + wm * 16 + g + ((e >> 1) ? 8 : 0);
            int col = bn + wn * 32 + nt * 8 + tg * 2 + (e & 1);
            if (row >= M) continue;
            float v = acc[nt][e];
            if (EPI == 0) {
                C[(size_t)row * N + col] = v + (bias ? bias[col] : 0.f);
            } else {  // EPI == 2
                if (col < H4) {
                    u[(size_t)row * H4 + col] = v + be[col] - pmS[(size_t)row * NW + col];
                } else {
                    int cc = col - H4;
                    hkbuf[(size_t)row * HD + cc] =
                        fmaxf(v + b_hk[cc], 0.f) * W_d1[cc];
                }
            }
        }
}

// ---------------- persistent statement LSTM (grid = 96) -----------------------
#define LSTM_SMEM_BYTES (2 * 18432 * 4)
__global__ __launch_bounds__(256)
void lstm_persist_kernel(const float* __restrict__ xw, const float* __restrict__ Wt,
                         float* __restrict__ c0, float* __restrict__ hA,
                         float* __restrict__ hB) {
    extern __shared__ float dyn[];
    float* sW = dyn;
    float* sA = dyn + 18432;
    unsigned gen = 0;
    const int tid = threadIdx.x;
    const int lane = tid & 31, warp = tid >> 5;
    const int wm = warp >> 1, wn = warp & 1;
    const int g = lane >> 2, tg = lane & 3;
    const int bm = (blockIdx.x % 6) * 64;
    const int bn = (blockIdx.x / 6) * 64;
    const int ar_r = tid >> 3, ar_kc = (tid & 7) << 2;
    const int br_kk = tid >> 4, br_c = (tid & 15) << 2;

#pragma unroll
    for (int ch = 0; ch < 8; ch++) {
        int k0 = ch * 32;
        float* sWc = sW + ch * (32 * SB_STRIDE);
#pragma unroll
        for (int l = 0; l < 2; l++) {
            int kk = br_kk + l * 16;
            float4 v = *(const float4*)(Wt + (size_t)(k0 + kk) * H4 + bn + br_c);
            float* d = sWc + kk * SB_STRIDE + br_c;
            d[0] = to_tf32(v.x); d[1] = to_tf32(v.y);
            d[2] = to_tf32(v.z); d[3] = to_tf32(v.w);
        }
    }

#pragma unroll
    for (int l = 0; l < 4; l++) {
        int pi = tid + l * 256;
        int lr = pi & 63, lh = pi >> 6;
        int row = bm + lr, hh = (bn >> 2) + lh;
        float4 x4 = *(const float4*)(xw + (size_t)row * (TT * H4) + hh * 4);
        float c2 = sigf(x4.x) * tanhr(x4.z);
        size_t idx = (size_t)row * HD + hh;
        c0[idx] = c2;
        hA[idx] = sigf(x4.w) * tanhr(c2);
    }
    grid_bar(&g_barL, &gen, gridDim.x);

    const float* hs = hA;
    float* hd = hB;
    for (int t = 1; t < TT; t++) {
#pragma unroll
        for (int ch = 0; ch < 8; ch++) {
            int k0 = ch * 32;
            float* sAc = sA + ch * (64 * SA_STRIDE);
#pragma unroll
            for (int l = 0; l < 2; l++) {
                int r = ar_r + l * 32;
                float4 v = __ldcg((const float4*)(hs + (size_t)(bm + r) * HD + k0 + ar_kc));
                float* d = sAc + r * SA_STRIDE + ar_kc;
                d[0] = to_tf32(v.x); d[1] = to_tf32(v.y);
                d[2] = to_tf32(v.z); d[3] = to_tf32(v.w);
            }
        }
        __syncthreads();

        float acc[4][4];
#pragma unroll
        for (int a = 0; a < 4; a++)
#pragma unroll
            for (int b = 0; b < 4; b++) acc[a][b] = 0.f;
#pragma unroll
        for (int it = 0; it < 8; it++) {
            const float* sAc = sA + it * (64 * SA_STRIDE);
            const float* sWc = sW + it * (32 * SB_STRIDE);
#pragma unroll
            for (int k8 = 0; k8 < 4; k8++) {
                int kb = k8 * 8;
                float a0 = sAc[(wm * 16 + g) * SA_STRIDE + kb + tg];
                float a1 = sAc[(wm * 16 + g + 8) * SA_STRIDE + kb + tg];
                float a2 = sAc[(wm * 16 + g) * SA_STRIDE + kb + tg + 4];
                float a3 = sAc[(wm * 16 + g + 8) * SA_STRIDE + kb + tg + 4];
#pragma unroll
                for (int nt = 0; nt < 4; nt++) {
                    int nc = wn * 32 + nt * 8 + g;
                    float b0 = sWc[(kb + tg) * SB_STRIDE + nc];
                    float b1 = sWc[(kb + tg + 4) * SB_STRIDE + nc];
                    mma_tf32(acc[nt][0], acc[nt][1], acc[nt][2], acc[nt][3],
                             a0, a1, a2, a3, b0, b1);
                }
            }
        }
        __syncthreads();

        float* buf = sA;
#pragma unroll
        for (int nt = 0; nt < 4; nt++)
#pragma unroll
            for (int e = 0; e < 4; e++) {
                int lr = wm * 16 + g + ((e >> 1) ? 8 : 0);
                int lc = wn * 32 + nt * 8 + tg * 2 + (e & 1);
                buf[lr * BUF_STRIDE + lc] = acc[nt][e];
            }
        __syncthreads();
#pragma unroll
        for (int l = 0; l < 4; l++) {
            int pi = tid + l * 256;
            int lr = pi & 63, lh = pi >> 6;
            int row = bm + lr, hh = (bn >> 2) + lh;
            float4 z4 = *(const float4*)(buf + lr * BUF_STRIDE + lh * 4);
            float4 x4 = *(const float4*)(xw + (size_t)row * (TT * H4) + t * H4 + hh * 4);
            float zi = z4.x + x4.x;
            float zf = z4.y + x4.y;
            float zg = z4.z + x4.z;
            float zo = z4.w + x4.w;
            size_t idx = (size_t)row * HD + hh;
            float cp = c0[idx];
            float c2 = sigf(zf) * cp + sigf(zi) * tanhr(zg);
            c0[idx] = c2;
            hd[idx] = sigf(zo) * tanhr(c2);
        }
        grid_bar(&g_barL, &gen, gridDim.x);
        const float* tmp = hs; hs = hd; hd = (float*)tmp;
    }
}

// ---------------- merged prep ------------------------------------------------
__global__ void prep_kernel(const float* __restrict__ Wh_s, const float* __restrict__ Wx_s,
                            const float* __restrict__ b_s,
                            const float* __restrict__ Wh_e, const float* __restrict__ W_hk,
                            const float* __restrict__ Wx_e, const float* __restrict__ W_sd,
                            const float* __restrict__ b_se, const float* __restrict__ b_e,
                            const float* __restrict__ b_sd, const float* __restrict__ init_b,
                            float* __restrict__ Wt, float* __restrict__ Wxt,
                            float* __restrict__ bst,
                            float* __restrict__ B1, float* __restrict__ B2,
                            float* __restrict__ be, float* __restrict__ bs,
                            float* __restrict__ uInit) {
    int idx = blockIdx.x * 256 + threadIdx.x;
    if (idx == 0) g_barL = 0u;
    if (idx < HD * H4) {
        int k = idx / H4, col = idx % H4;
        int g = col / HD, hh = col % HD;
        Wt[(size_t)k * H4 + hh * 4 + g] = Wh_s[idx];
        Wxt[(size_t)k * H4 + hh * 4 + g] = Wx_s[idx];
    }
    if (idx < H4) {
        int g = idx / HD, hh = idx % HD;
        bst[hh * 4 + g] = b_s[idx];
    }
    if (idx < HD * NW) {
        int k = idx / NW, c = idx % NW;
        B1[idx] = (c < H4) ? Wh_e[(size_t)k * H4 + c] : W_hk[(size_t)k * HD + (c - H4)];
        B2[idx] = (c < H4) ? Wx_e[(size_t)k * H4 + c] : W_sd[(size_t)k * HD + (c - H4)];
    }
    if (idx < H4) {
        float acc = b_e[idx];
        for (int k = 0; k < HD; k++) acc += b_se[k] * Wx_e[(size_t)k * H4 + idx];
        be[idx] = acc;
    } else if (idx < H4 + HD) {
        int c = idx - H4;
        float acc = b_sd[c];
        for (int k = 0; k < HD; k++) acc += b_se[k] * W_sd[(size_t)k * HD + c];
        bs[c] = acc;
    } else if (idx >= 2048 && idx < 2048 + H4) {
        int n = idx - 2048;   // uInit = init_b@Wh_e + b_se@Wx_e + b_e
        float acc = b_e[n];
        for (int k = 0; k < HD; k++) acc += init_b[k] * Wh_e[(size_t)k * H4 + n];
        for (int k = 0; k < HD; k++) acc += b_se[k] * Wx_e[(size_t)k * H4 + n];
        uInit[n] = acc;
    }
}

// ---------------- cumsum with batched prefetch --------------------------------
__global__ void cumsum_kernel(const float* __restrict__ stmt, float* __restrict__ pref) {
    int b = blockIdx.x, hh = threadIdx.x;
    float acc = 0.f;
    pref[(size_t)(b * NN) * HD + hh] = 0.f;
    for (int k0 = 0; k0 < NSS; k0 += 8) {
        float v[8];
#pragma unroll
        for (int l = 0; l < 8; l++)
            v[l] = stmt[(size_t)(b * NSS + k0 + l) * HD + hh];
#pragma unroll
        for (int l = 0; l < 8; l++) {
            acc += v[l];
            pref[(size_t)(b * NN + k0 + l + 1) * HD + hh] = acc;
        }
    }
}

// ---------------- S2 only (exec init no longer needed) ------------------------
__global__ void s2_kernel(const float* __restrict__ pmS, const float* __restrict__ bs,
                          const float* __restrict__ W_d1, float* __restrict__ S2) {
    int bi = blockIdx.x;
    int b = bi / NN;
    int lane = threadIdx.x & 31, warp = threadIdx.x >> 5;
    const float* pi = pmS + (size_t)bi * NW + H4;
    for (int j = warp; j < NN; j += 4) {
        const float* pj = pmS + (size_t)(b * NN + j) * NW + H4;
        float acc = 0.f;
#pragma unroll
        for (int l = 0; l < 8; l++) {
            int hh = lane + l * 32;
            float v = pj[hh] - pi[hh] + bs[hh];
            acc += fmaxf(v, 0.f) * W_d1[HD + hh];
        }
        for (int o = 16; o; o >>= 1) acc += __shfl_xor_sync(0xFFFFFFFFu, acc, o);
        if (lane == 0) S2[(size_t)bi * NN + j] = acc;
    }
}

// ---------------- layer 0 closed form -----------------------------------------
// w[0][1]=1 only: node1 = LSTM(init state, z = pm4[b,1] + uInit); rest zero.
__global__ void layer0_kernel(const float* __restrict__ pmS, const float* __restrict__ uInit,
                              const float* __restrict__ init_a,
                              float* __restrict__ cD, float* __restrict__ hD,
                              float* __restrict__ pD) {
    int bj = blockIdx.x, b = bj / NN, j = bj % NN;
    int hh = threadIdx.x;
    if (hh == 0) pD[bj] = (j == 1) ? 1.f : 0.f;
    size_t idx = (size_t)bj * HD + hh;
    if (j != 1) { cD[idx] = 0.f; hD[idx] = 0.f; return; }
    const float* pj = pmS + (size_t)(b * NN + 1) * NW;
    float zi = pj[hh]          + uInit[hh];
    float zf = pj[HD + hh]     + uInit[HD + hh];
    float zg = pj[2 * HD + hh] + uInit[2 * HD + hh];
    float zo = pj[3 * HD + hh] + uInit[3 * HD + hh];
    float c2 = sigf(zf) * init_a[hh] + sigf(zi) * tanhr(zg);
    float h2 = sigf(zo) * tanhr(c2);
    float inv = __fdividef(1.f, 1.f + 1e-7f);
    cD[idx] = c2 * inv;
    hD[idx] = h2 * inv;
}

// ---------------- per-layer softmax (layers 1..4) ------------------------------
__global__ void softmax_kernel(const float* __restrict__ hkbuf,
                               const float* __restrict__ S2, const float* __restrict__ b_d1,
                               const float* __restrict__ p, const int* __restrict__ clen,
                               int layer, float* __restrict__ w) {
    int bi = blockIdx.x, b = bi / NN, i = bi % NN;
    int tid = threadIdx.x;   // 256
    float pv = p[bi];
    if (pv == 0.f) {            // row contributes nothing; write zeros fast
        if (tid < NN) w[(size_t)bi * NN + tid] = 0.f;
        return;
    }
    __shared__ float red[256];
    red[tid] = hkbuf[(size_t)bi * HD + tid];
    __syncthreads();
    for (int s = 128; s > 0; s >>= 1) {
        if (tid < s) red[tid] += red[tid + s];
        __syncthreads();
    }
    float a = red[0];
    __syncthreads();

    int len = clen[b] / TT;
    int j = tid;
    bool m = (j < NN) && (((j > i) && (j <= len)) || (j == len));
    float logit = m ? (a + S2[(size_t)bi * NN + j] + b_d1[0]) : -1e30f;
    red[tid] = logit; __syncthreads();
    for (int s = 128; s > 0; s >>= 1) {
        if (tid < s) red[tid] = fmaxf(red[tid], red[tid + s]);
        __syncthreads();
    }
    float mx = red[0]; __syncthreads();
    float e = m ? __expf(logit - mx) : 0.f;
    red[tid] = e; __syncthreads();
    for (int s = 128; s > 0; s >>= 1) {
        if (tid < s) red[tid] += red[tid + s];
        __syncthreads();
    }
    float sum = red[0];
    if (j < NN) w[(size_t)bi * NN + j] = pv * __fdividef(e, sum);
}

// ---------------- gated aggregation (lastLayer: w[i][len] = p[i]) -------------
__global__ void agg_kernel(const float* __restrict__ w, const float* __restrict__ pmS,
                           const float* __restrict__ u,
                           const float* __restrict__ cIn, const float* __restrict__ hIn,
                           float* __restrict__ cOut, float* __restrict__ hOut,
                           float* __restrict__ pOut,
                           const float* __restrict__ p, const int* __restrict__ clen,
                           int lastLayer) {
    int bj = blockIdx.x, b = bj / NN, j = bj % NN;
    int hh = threadIdx.x;  // 256
    __shared__ float sw[NN];
    if (hh < NN) {
        if (lastLayer) {
            int len = clen[b] / TT;
            sw[hh] = (j == len) ? p[b * NN + hh] : 0.f;
        } else {
            sw[hh] = w[((size_t)(b * NN + hh)) * NN + j];
        }
    }
    __syncthreads();
    const float* pj = pmS + (size_t)bj * NW;
    float zj0 = pj[hh], zj1 = pj[HD + hh], zj2 = pj[2 * HD + hh], zj3 = pj[3 * HD + hh];
    float accC = 0.f, accH = 0.f, wsum = 0.f;
    for (int i = 0; i < NN; i++) {
        float wi = sw[i];
        wsum += wi;
        if (wi == 0.f) continue;
        int ri = b * NN + i;
        float cp, hp;
        if (j > i) {
            const float* ui = u + (size_t)ri * H4;
            float zi = zj0 + ui[hh];
            float zf = zj1 + ui[HD + hh];
            float zg = zj2 + ui[2 * HD + hh];
            float zo = zj3 + ui[3 * HD + hh];
            float cold = cIn[(size_t)ri * HD + hh];
            cp = sigw(zf) * cold + sigw(zi) * tanhw(zg);
            hp = sigw(zo) * tanhw(cp);
        } else {
            cp = cIn[(size_t)ri * HD + hh];
            hp = hIn[(size_t)ri * HD + hh];
        }
        accC += wi * cp;
        accH += wi * hp;
    }
    float inv = __fdividef(1.f, wsum + 1e-7f);
    cOut[(size_t)bj * HD + hh] = accC * inv;
    hOut[(size_t)bj * HD + hh] = accH * inv;
    if (hh == 0) pOut[bj] = wsum;
}

// ------------------------------------------------------------------------------
static float* sym(const void* s) {
    void* p = nullptr;
    cudaGetSymbolAddress(&p, s);
    return (float*)p;
}

extern "C" void kernel_launch(void* const* d_in, const int* in_sizes, int n_in,
                              void* d_out, int out_size) {
    const int*   ids    = (const int*)d_in[0];
    const int*   clen   = (const int*)d_in[1];
    const float* embed  = (const float*)d_in[2];
    const float* Wx_s   = (const float*)d_in[3];
    const float* Wh_s   = (const float*)d_in[4];
    const float* b_s    = (const float*)d_in[5];
    const float* W_se   = (const float*)d_in[6];
    const float* b_se   = (const float*)d_in[7];
    const float* Wx_e   = (const float*)d_in[8];
    const float* Wh_e   = (const float*)d_in[9];
    const float* b_e    = (const float*)d_in[10];
    const float* W_hk   = (const float*)d_in[11];
    const float* b_hk   = (const float*)d_in[12];
    const float* W_sd   = (const float*)d_in[13];
    const float* b_sd   = (const float*)d_in[14];
    const float* W_d1   = (const float*)d_in[15];
    const float* b_d1   = (const float*)d_in[16];
    const float* init_a = (const float*)d_in[17];
    const float* init_b = (const float*)d_in[18];

    float* xw    = sym(g_xw);
    float* Wt    = sym(g_Wt);
    float* Wxt   = sym(g_Wxt);
    float* bst   = sym(g_bst);
    float* B1    = sym(g_B1);
    float* B2    = sym(g_B2);
    float* c0    = sym(g_c0);
    float* hA    = sym(g_hA);
    float* hB    = sym(g_hB);
    float* pref  = sym(g_pref);
    float* MeMs  = sym(g_MeMs);
    float* pmS   = sym(g_pmS);
    float* be    = sym(g_be);
    float* bs    = sym(g_bs);
    float* uInit = sym(g_uInit);
    float* S2    = sym(g_S2);
    float* uBuf  = sym(g_u);
    float* hk    = sym(g_hk);
    float* wM    = sym(g_w);
    float* cX    = sym(g_cX);
    float* hX    = sym(g_hX);
    float* cY    = sym(g_cY);
    float* hY    = sym(g_hY);
    float* pX    = sym(g_pX);
    float* pY    = sym(g_pY);

    cudaFuncSetAttribute(lstm_persist_kernel,
                         cudaFuncAttributeMaxDynamicSharedMemorySize, LSTM_SMEM_BYTES);

    // 0) merged prep (also computes uInit, resets barrier)
    prep_kernel<<<(HD * NW + 255) / 256, 256>>>(
        Wh_s, Wx_s, b_s, Wh_e, W_hk, Wx_e, W_sd, b_se, b_e, b_sd, init_b,
        Wt, Wxt, bst, B1, B2, be, bs, uInit);

    // 1) token projection (gate-interleaved output)
    mma_gemm<0><<<dim3(TOK / 64, H4 / 64), 256>>>(
        embed, ids, Wxt, bst, xw, TOK, H4,
        nullptr, nullptr, nullptr, nullptr, nullptr, nullptr, nullptr);

    // 2) statement LSTM — persistent (final h lands in hB)
    lstm_persist_kernel<<<96, 256, LSTM_SMEM_BYTES>>>(xw, Wt, c0, hA, hB);

    // 3) prefix sums
    cumsum_kernel<<<BB, HD>>>(hB, pref);

    // 4) composed tables
    mma_gemm<0><<<dim3(HD / 64, NW / 64), 256>>>(
        W_se, nullptr, B2, nullptr, MeMs, HD, NW,
        nullptr, nullptr, nullptr, nullptr, nullptr, nullptr, nullptr);
    mma_gemm<0><<<dim3((ROWS + 63) / 64, NW / 64), 256>>>(
        pref, nullptr, MeMs, nullptr, pmS, ROWS, NW,
        nullptr, nullptr, nullptr, nullptr, nullptr, nullptr, nullptr);

    // 5) S2
    s2_kernel<<<ROWS, 128>>>(pmS, bs, W_d1, S2);

    // 6) layer 0: closed form -> (cX, hX, pX)
    layer0_kernel<<<ROWS, 256>>>(pmS, uInit, init_a, cX, hX, pX);

    // 7) layers 1..5
    float *cS = cX, *hS = hX, *pS = pX, *cD = cY, *hD2 = hY, *pD = pY;
    for (int layer = 1; layer < NLAY; layer++) {
        int last = (layer == NLAY - 1);
        mma_gemm<2><<<dim3((ROWS + 63) / 64, NW / 64), 256>>>(
            hS, nullptr, B1, nullptr, nullptr, ROWS, NW,
            be, pmS, b_hk, W_d1, uBuf, hk, pS);
        if (!last)
            softmax_kernel<<<ROWS, 256>>>(hk, S2, b_d1, pS, clen, layer, wM);
        float* hOutPtr = last ? (float*)d_out : hD2;
        agg_kernel<<<ROWS, 256>>>(wM, pmS, uBuf, cS, hS, cD, hOutPtr, pD,
                                  pS, clen, last);
        float* t;
        t = cS; cS = cD; cD = t;
        t = hS; hS = hD2; hD2 = t;
        t = pS; pS = pD; pD = t;
    }
}

// round 14
// speedup vs baseline: 1.0745x; 1.0357x over previous
#include <cuda_runtime.h>
#include <cstdio>
#include <cstdint>

#define BB 4
#define NSS 96
#define TT 8
#define HD 256
#define H4 1024
#define NW 1280
#define NN 97
#define NLAY 6
#define ROWS (BB*NN)     // 388
#define SEQS (BB*NSS)    // 384
#define TOK  (SEQS*TT)   // 3072

// ---------------- scratch -----------------------------------------------------
__device__ float g_xw[TOK*H4];         // token proj, GATE-INTERLEAVED [row][hh*4+g]
__device__ float g_Wt[HD*H4];          // Wh_s gate-interleaved [k][hh*4+g]
__device__ float g_Wxt[HD*H4];         // Wx_s gate-interleaved
__device__ float g_bst[H4];            // b_s gate-interleaved
__device__ float g_B1[HD*NW];          // [Wh_e | W_hk]
__device__ float g_B2[HD*NW];          // [Wx_e | W_sd]
__device__ float g_c0[SEQS*HD];
__device__ float g_hA[SEQS*HD];
__device__ float g_hB[SEQS*HD];
__device__ float g_pref[ROWS*HD];
__device__ float g_MeMs[HD*NW];
__device__ float g_pmS[ROWS*NW];       // cols 0-1023 = pm4, 1024+ = prS
__device__ float g_be[H4];
__device__ float g_bs[HD];
__device__ float g_uInit[H4];          // init_b@Wh_e + b_se@Wx_e + b_e
__device__ float g_S2[BB*NN*NN];
__device__ float g_u[ROWS*H4];
__device__ float g_hk[ROWS*HD];
__device__ float g_w[BB*NN*NN];
__device__ float g_cX[ROWS*HD], g_hX[ROWS*HD];
__device__ float g_cY[ROWS*HD], g_hY[ROWS*HD];
__device__ float g_pX[ROWS], g_pY[ROWS];
__device__ unsigned g_barL;            // lstm grid-barrier counter

// exp-based gates (statement LSTM / layer0 path)
__device__ __forceinline__ float sigf(float x) {
    return __fdividef(1.0f, 1.0f + __expf(-x));
}
__device__ __forceinline__ float tanhr(float x) {
    return 2.0f * __fdividef(1.0f, 1.0f + __expf(-2.0f * x)) - 1.0f;
}
// HW-tanh gates (agg hot loop)
__device__ __forceinline__ float tanhw(float x) {
    float y;
    asm("tanh.approx.f32 %0, %1;" : "=f"(y) : "f"(x));
    return y;
}
__device__ __forceinline__ float sigw(float x) {
    return fmaf(0.5f, tanhw(0.5f * x), 0.5f);
}

__device__ __forceinline__ float to_tf32(float x) {
    uint32_t o;
    asm("cvt.rna.tf32.f32 %0, %1;" : "=r"(o) : "f"(x));
    return __uint_as_float(o);
}

__device__ __forceinline__ void mma_tf32(float& c0, float& c1, float& c2, float& c3,
                                         float a0, float a1, float a2, float a3,
                                         float b0, float b1) {
    asm volatile(
        "mma.sync.aligned.m16n8k8.row.col.f32.tf32.tf32.f32 "
        "{%0,%1,%2,%3},{%4,%5,%6,%7},{%8,%9},{%0,%1,%2,%3};"
        : "+f"(c0), "+f"(c1), "+f"(c2), "+f"(c3)
        : "r"(__float_as_uint(a0)), "r"(__float_as_uint(a1)),
          "r"(__float_as_uint(a2)), "r"(__float_as_uint(a3)),
          "r"(__float_as_uint(b0)), "r"(__float_as_uint(b1)));
}

// generation-based grid barrier
__device__ __forceinline__ void grid_bar(unsigned* ctr, unsigned* gen, unsigned nb) {
    __syncthreads();
    if (threadIdx.x == 0) {
        *gen += nb;
        unsigned target = *gen;
        __threadfence();
        atomicAdd(ctr, 1u);
        while (*(volatile unsigned*)ctr < target) __nanosleep(64);
        __threadfence();
    }
    __syncthreads();
}

// ---------------- tf32 MMA GEMM, K=256, tile 64x64, double-buffered -----------
// EPI: 0 = plain (+opt bias), 2 = u + hk (with p-based tile skip)
#define SA_STRIDE 36
#define SB_STRIDE 72
#define BUF_STRIDE 68
#define TILE_FLOATS (64*SA_STRIDE + 32*SB_STRIDE)   // 4608
template<int EPI>
__global__ __launch_bounds__(256)
void mma_gemm(const float* __restrict__ A, const int* __restrict__ gidx,
              const float* __restrict__ B, const float* __restrict__ bias,
              float* __restrict__ C, int M, int N,
              const float* __restrict__ be, const float* __restrict__ pmS,
              const float* __restrict__ b_hk, const float* __restrict__ W_d1,
              float* __restrict__ u, float* __restrict__ hkbuf,
              const float* __restrict__ pcheck) {
    __shared__ float smem[2 * TILE_FLOATS];
    __shared__ int s_active;
    const int tid = threadIdx.x;
    const int lane = tid & 31, warp = tid >> 5;
    const int wm = warp >> 1, wn = warp & 1;
    const int g = lane >> 2, tg = lane & 3;
    const int bm = blockIdx.x * 64, bn = blockIdx.y * 64;

    if (EPI == 2) {
        if (tid == 0) s_active = 0;
        __syncthreads();
        if (tid < 64) {
            int row = bm + tid;
            if (row < M && pcheck[row] != 0.f) s_active = 1;
        }
        __syncthreads();
        if (!s_active) return;   // u/hk rows stale; unread because p==0 downstream
    }

    const int ar_r  = tid >> 3;
    const int ar_kc = (tid & 7) << 2;
    const int br_kk = tid >> 4;
    const int br_c  = (tid & 15) << 2;

    float4 va[2], vb[2];
    auto load_regs = [&](int k0) {
#pragma unroll
        for (int l = 0; l < 2; l++) {
            int r = ar_r + l * 32;
            int row = bm + r;
            float4 v = make_float4(0.f, 0.f, 0.f, 0.f);
            if (row < M) {
                int ar = gidx ? gidx[row] : row;
                v = *(const float4*)(A + (size_t)ar * HD + k0 + ar_kc);
            }
            va[l] = v;
        }
#pragma unroll
        for (int l = 0; l < 2; l++) {
            int kk = br_kk + l * 16;
            vb[l] = *(const float4*)(B + (size_t)(k0 + kk) * N + bn + br_c);
        }
    };
    auto store_smem = [&](int buf) {
        float* sA = smem + buf * TILE_FLOATS;
        float* sB = sA + 64 * SA_STRIDE;
#pragma unroll
        for (int l = 0; l < 2; l++) {
            float* d = sA + (ar_r + l * 32) * SA_STRIDE + ar_kc;
            d[0] = to_tf32(va[l].x); d[1] = to_tf32(va[l].y);
            d[2] = to_tf32(va[l].z); d[3] = to_tf32(va[l].w);
        }
#pragma unroll
        for (int l = 0; l < 2; l++) {
            float* d = sB + (br_kk + l * 16) * SB_STRIDE + br_c;
            d[0] = to_tf32(vb[l].x); d[1] = to_tf32(vb[l].y);
            d[2] = to_tf32(vb[l].z); d[3] = to_tf32(vb[l].w);
        }
    };

    float acc[4][4];
#pragma unroll
    for (int a = 0; a < 4; a++)
#pragma unroll
        for (int b = 0; b < 4; b++) acc[a][b] = 0.f;

    load_regs(0);
    store_smem(0);
    __syncthreads();

    constexpr int NT = HD / 32;
#pragma unroll
    for (int it = 0; it < NT; it++) {
        if (it + 1 < NT) load_regs((it + 1) * 32);
        const float* sA = smem + (it & 1) * TILE_FLOATS;
        const float* sB = sA + 64 * SA_STRIDE;
#pragma unroll
        for (int k8 = 0; k8 < 4; k8++) {
            int kb = k8 * 8;
            float a0 = sA[(wm * 16 + g) * SA_STRIDE + kb + tg];
            float a1 = sA[(wm * 16 + g + 8) * SA_STRIDE + kb + tg];
            float a2 = sA[(wm * 16 + g) * SA_STRIDE + kb + tg + 4];
            float a3 = sA[(wm * 16 + g + 8) * SA_STRIDE + kb + tg + 4];
#pragma unroll
            for (int nt = 0; nt < 4; nt++) {
                int nc = wn * 32 + nt * 8 + g;
                float b0 = sB[(kb + tg) * SB_STRIDE + nc];
                float b1 = sB[(kb + tg + 4) * SB_STRIDE + nc];
                mma_tf32(acc[nt][0], acc[nt][1], acc[nt][2], acc[nt][3],
                         a0, a1, a2, a3, b0, b1);
            }
        }
        if (it + 1 < NT) {
            store_smem((it + 1) & 1);
            __syncthreads();
        }
    }

#pragma unroll
    for (int nt = 0; nt < 4; nt++)
#pragma unroll
        for (int e = 0; e < 4; e++) {
            int row = bm + wm * 16 + g + ((e >> 1) ? 8 : 0);
            int col = bn + wn * 32 + nt * 8 + tg * 2 + (e & 1);
            if (row >= M) continue;
            float v = acc[nt][e];
            if (EPI == 0) {
                C[(size_t)row * N + col] = v + (bias ? bias[col] : 0.f);
            } else {  // EPI == 2
                if (col < H4) {
                    u[(size_t)row * H4 + col] = v + be[col] - pmS[(size_t)row * NW + col];
                } else {
                    int cc = col - H4;
                    hkbuf[(size_t)row * HD + cc] =
                        fmaxf(v + b_hk[cc], 0.f) * W_d1[cc];
                }
            }
        }
}

// ---------------- persistent statement LSTM (grid = 96) -----------------------
#define LSTM_SMEM_BYTES (2 * 18432 * 4)
__global__ __launch_bounds__(256)
void lstm_persist_kernel(const float* __restrict__ xw, const float* __restrict__ Wt,
                         float* __restrict__ c0, float* __restrict__ hA,
                         float* __restrict__ hB) {
    extern __shared__ float dyn[];
    float* sW = dyn;
    float* sA = dyn + 18432;
    unsigned gen = 0;
    const int tid = threadIdx.x;
    const int lane = tid & 31, warp = tid >> 5;
    const int wm = warp >> 1, wn = warp & 1;
    const int g = lane >> 2, tg = lane & 3;
    const int bm = (blockIdx.x % 6) * 64;
    const int bn = (blockIdx.x / 6) * 64;
    const int ar_r = tid >> 3, ar_kc = (tid & 7) << 2;
    const int br_kk = tid >> 4, br_c = (tid & 15) << 2;

#pragma unroll
    for (int ch = 0; ch < 8; ch++) {
        int k0 = ch * 32;
        float* sWc = sW + ch * (32 * SB_STRIDE);
#pragma unroll
        for (int l = 0; l < 2; l++) {
            int kk = br_kk + l * 16;
            float4 v = *(const float4*)(Wt + (size_t)(k0 + kk) * H4 + bn + br_c);
            float* d = sWc + kk * SB_STRIDE + br_c;
            d[0] = to_tf32(v.x); d[1] = to_tf32(v.y);
            d[2] = to_tf32(v.z); d[3] = to_tf32(v.w);
        }
    }

#pragma unroll
    for (int l = 0; l < 4; l++) {
        int pi = tid + l * 256;
        int lr = pi & 63, lh = pi >> 6;
        int row = bm + lr, hh = (bn >> 2) + lh;
        float4 x4 = *(const float4*)(xw + (size_t)row * (TT * H4) + hh * 4);
        float c2 = sigf(x4.x) * tanhr(x4.z);
        size_t idx = (size_t)row * HD + hh;
        c0[idx] = c2;
        hA[idx] = sigf(x4.w) * tanhr(c2);
    }
    grid_bar(&g_barL, &gen, gridDim.x);

    const float* hs = hA;
    float* hd = hB;
    for (int t = 1; t < TT; t++) {
#pragma unroll
        for (int ch = 0; ch < 8; ch++) {
            int k0 = ch * 32;
            float* sAc = sA + ch * (64 * SA_STRIDE);
#pragma unroll
            for (int l = 0; l < 2; l++) {
                int r = ar_r + l * 32;
                float4 v = __ldcg((const float4*)(hs + (size_t)(bm + r) * HD + k0 + ar_kc));
                float* d = sAc + r * SA_STRIDE + ar_kc;
                d[0] = to_tf32(v.x); d[1] = to_tf32(v.y);
                d[2] = to_tf32(v.z); d[3] = to_tf32(v.w);
            }
        }
        __syncthreads();

        float acc[4][4];
#pragma unroll
        for (int a = 0; a < 4; a++)
#pragma unroll
            for (int b = 0; b < 4; b++) acc[a][b] = 0.f;
#pragma unroll
        for (int it = 0; it < 8; it++) {
            const float* sAc = sA + it * (64 * SA_STRIDE);
            const float* sWc = sW + it * (32 * SB_STRIDE);
#pragma unroll
            for (int k8 = 0; k8 < 4; k8++) {
                int kb = k8 * 8;
                float a0 = sAc[(wm * 16 + g) * SA_STRIDE + kb + tg];
                float a1 = sAc[(wm * 16 + g + 8) * SA_STRIDE + kb + tg];
                float a2 = sAc[(wm * 16 + g) * SA_STRIDE + kb + tg + 4];
                float a3 = sAc[(wm * 16 + g + 8) * SA_STRIDE + kb + tg + 4];
#pragma unroll
                for (int nt = 0; nt < 4; nt++) {
                    int nc = wn * 32 + nt * 8 + g;
                    float b0 = sWc[(kb + tg) * SB_STRIDE + nc];
                    float b1 = sWc[(kb + tg + 4) * SB_STRIDE + nc];
                    mma_tf32(acc[nt][0], acc[nt][1], acc[nt][2], acc[nt][3],
                             a0, a1, a2, a3, b0, b1);
                }
            }
        }
        __syncthreads();

        float* buf = sA;
#pragma unroll
        for (int nt = 0; nt < 4; nt++)
#pragma unroll
            for (int e = 0; e < 4; e++) {
                int lr = wm * 16 + g + ((e >> 1) ? 8 : 0);
                int lc = wn * 32 + nt * 8 + tg * 2 + (e & 1);
                buf[lr * BUF_STRIDE + lc] = acc[nt][e];
            }
        __syncthreads();
#pragma unroll
        for (int l = 0; l < 4; l++) {
            int pi = tid + l * 256;
            int lr = pi & 63, lh = pi >> 6;
            int row = bm + lr, hh = (bn >> 2) + lh;
            float4 z4 = *(const float4*)(buf + lr * BUF_STRIDE + lh * 4);
            float4 x4 = *(const float4*)(xw + (size_t)row * (TT * H4) + t * H4 + hh * 4);
            float zi = z4.x + x4.x;
            float zf = z4.y + x4.y;
            float zg = z4.z + x4.z;
            float zo = z4.w + x4.w;
            size_t idx = (size_t)row * HD + hh;
            float cp = c0[idx];
            float c2 = sigf(zf) * cp + sigf(zi) * tanhr(zg);
            c0[idx] = c2;
            hd[idx] = sigf(zo) * tanhr(c2);
        }
        grid_bar(&g_barL, &gen, gridDim.x);
        const float* tmp = hs; hs = hd; hd = (float*)tmp;
    }
}

// ---------------- merged prep ------------------------------------------------
__global__ void prep_kernel(const float* __restrict__ Wh_s, const float* __restrict__ Wx_s,
                            const float* __restrict__ b_s,
                            const float* __restrict__ Wh_e, const float* __restrict__ W_hk,
                            const float* __restrict__ Wx_e, const float* __restrict__ W_sd,
                            const float* __restrict__ b_se, const float* __restrict__ b_e,
                            const float* __restrict__ b_sd, const float* __restrict__ init_b,
                            float* __restrict__ Wt, float* __restrict__ Wxt,
                            float* __restrict__ bst,
                            float* __restrict__ B1, float* __restrict__ B2,
                            float* __restrict__ be, float* __restrict__ bs,
                            float* __restrict__ uInit) {
    int idx = blockIdx.x * 256 + threadIdx.x;
    if (idx == 0) g_barL = 0u;
    if (idx < HD * H4) {
        int k = idx / H4, col = idx % H4;
        int g = col / HD, hh = col % HD;
        Wt[(size_t)k * H4 + hh * 4 + g] = Wh_s[idx];
        Wxt[(size_t)k * H4 + hh * 4 + g] = Wx_s[idx];
    }
    if (idx < H4) {
        int g = idx / HD, hh = idx % HD;
        bst[hh * 4 + g] = b_s[idx];
    }
    if (idx < HD * NW) {
        int k = idx / NW, c = idx % NW;
        B1[idx] = (c < H4) ? Wh_e[(size_t)k * H4 + c] : W_hk[(size_t)k * HD + (c - H4)];
        B2[idx] = (c < H4) ? Wx_e[(size_t)k * H4 + c] : W_sd[(size_t)k * HD + (c - H4)];
    }
    if (idx < H4) {
        float acc = b_e[idx];
        for (int k = 0; k < HD; k++) acc += b_se[k] * Wx_e[(size_t)k * H4 + idx];
        be[idx] = acc;
    } else if (idx < H4 + HD) {
        int c = idx - H4;
        float acc = b_sd[c];
        for (int k = 0; k < HD; k++) acc += b_se[k] * W_sd[(size_t)k * HD + c];
        bs[c] = acc;
    } else if (idx >= 2048 && idx < 2048 + H4) {
        int n = idx - 2048;   // uInit = init_b@Wh_e + b_se@Wx_e + b_e
        float acc = b_e[n];
        for (int k = 0; k < HD; k++) acc += init_b[k] * Wh_e[(size_t)k * H4 + n];
        for (int k = 0; k < HD; k++) acc += b_se[k] * Wx_e[(size_t)k * H4 + n];
        uInit[n] = acc;
    }
}

// ---------------- cumsum: two-level scan (4 blocks x 1024 threads) ------------
// Each thread: seg = tid>>8 (covers 24 statements), hh = tid&255.
#define SEG_LEN (NSS / 4)   // 24
__global__ __launch_bounds__(1024)
void cumsum_kernel(const float* __restrict__ stmt, float* __restrict__ pref) {
    int b = blockIdx.x;
    int seg = threadIdx.x >> 8;
    int hh = threadIdx.x & 255;
    __shared__ float tot[4][256];

    float v[SEG_LEN];
    float run = 0.f;
#pragma unroll
    for (int l = 0; l < SEG_LEN; l++) {
        float x = stmt[(size_t)(b * NSS + seg * SEG_LEN + l) * HD + hh];
        run += x;
        v[l] = run;               // local inclusive prefix
    }
    tot[seg][hh] = run;
    __syncthreads();
    float off = 0.f;
#pragma unroll
    for (int s = 0; s < 4; s++)
        if (s < seg) off += tot[s][hh];

    if (seg == 0) pref[(size_t)(b * NN) * HD + hh] = 0.f;
#pragma unroll
    for (int l = 0; l < SEG_LEN; l++)
        pref[(size_t)(b * NN + seg * SEG_LEN + l + 1) * HD + hh] = off + v[l];
}

// ---------------- merged S2 + layer-0 closed form (grid = ROWS, 256 thr) ------
__global__ void s2_layer0_kernel(const float* __restrict__ pmS, const float* __restrict__ bs,
                                 const float* __restrict__ W_d1, float* __restrict__ S2,
                                 const float* __restrict__ uInit,
                                 const float* __restrict__ init_a,
                                 float* __restrict__ cD, float* __restrict__ hD,
                                 float* __restrict__ pD) {
    int bi = blockIdx.x;
    int b = bi / NN, j0 = bi % NN;
    int tid = threadIdx.x;
    int lane = tid & 31, warp = tid >> 5;

    // --- layer 0 closed form: only node 1 per batch is live ---
    int hh = tid;
    if (hh == 0) pD[bi] = (j0 == 1) ? 1.f : 0.f;
    size_t idx = (size_t)bi * HD + hh;
    if (j0 != 1) {
        cD[idx] = 0.f; hD[idx] = 0.f;
    } else {
        const float* pj = pmS + (size_t)(b * NN + 1) * NW;
        float zi = pj[hh]          + uInit[hh];
        float zf = pj[HD + hh]     + uInit[HD + hh];
        float zg = pj[2 * HD + hh] + uInit[2 * HD + hh];
        float zo = pj[3 * HD + hh] + uInit[3 * HD + hh];
        float c2 = sigf(zf) * init_a[hh] + sigf(zi) * tanhr(zg);
        float h2 = sigf(zo) * tanhr(c2);
        float inv = __fdividef(1.f, 1.f + 1e-7f);
        cD[idx] = c2 * inv;
        hD[idx] = h2 * inv;
    }

    // --- S2 row bi (8 warps stride the j loop) ---
    const float* pi = pmS + (size_t)bi * NW + H4;
    for (int j = warp; j < NN; j += 8) {
        const float* pj = pmS + (size_t)(b * NN + j) * NW + H4;
        float acc = 0.f;
#pragma unroll
        for (int l = 0; l < 8; l++) {
            int h2 = lane + l * 32;
            float v = pj[h2] - pi[h2] + bs[h2];
            acc += fmaxf(v, 0.f) * W_d1[HD + h2];
        }
        for (int o = 16; o; o >>= 1) acc += __shfl_xor_sync(0xFFFFFFFFu, acc, o);
        if (lane == 0) S2[(size_t)bi * NN + j] = acc;
    }
}

// ---------------- per-layer softmax (layers 1..4) ------------------------------
__global__ void softmax_kernel(const float* __restrict__ hkbuf,
                               const float* __restrict__ S2, const float* __restrict__ b_d1,
                               const float* __restrict__ p, const int* __restrict__ clen,
                               int layer, float* __restrict__ w) {
    int bi = blockIdx.x, b = bi / NN, i = bi % NN;
    int tid = threadIdx.x;   // 256
    float pv = p[bi];
    if (pv == 0.f) {            // row contributes nothing; write zeros fast
        if (tid < NN) w[(size_t)bi * NN + tid] = 0.f;
        return;
    }
    __shared__ float red[256];
    red[tid] = hkbuf[(size_t)bi * HD + tid];
    __syncthreads();
    for (int s = 128; s > 0; s >>= 1) {
        if (tid < s) red[tid] += red[tid + s];
        __syncthreads();
    }
    float a = red[0];
    __syncthreads();

    int len = clen[b] / TT;
    int j = tid;
    bool m = (j < NN) && (((j > i) && (j <= len)) || (j == len));
    float logit = m ? (a + S2[(size_t)bi * NN + j] + b_d1[0]) : -1e30f;
    red[tid] = logit; __syncthreads();
    for (int s = 128; s > 0; s >>= 1) {
        if (tid < s) red[tid] = fmaxf(red[tid], red[tid + s]);
        __syncthreads();
    }
    float mx = red[0]; __syncthreads();
    float e = m ? __expf(logit - mx) : 0.f;
    red[tid] = e; __syncthreads();
    for (int s = 128; s > 0; s >>= 1) {
        if (tid < s) red[tid] += red[tid + s];
        __syncthreads();
    }
    float sum = red[0];
    if (j < NN) w[(size_t)bi * NN + j] = pv * __fdividef(e, sum);
}

// ---------------- gated aggregation (lastLayer: w[i][len] = p[i]) -------------
__global__ void agg_kernel(const float* __restrict__ w, const float* __restrict__ pmS,
                           const float* __restrict__ u,
                           const float* __restrict__ cIn, const float* __restrict__ hIn,
                           float* __restrict__ cOut, float* __restrict__ hOut,
                           float* __restrict__ pOut,
                           const float* __restrict__ p, const int* __restrict__ clen,
                           int lastLayer) {
    int bj = blockIdx.x, b = bj / NN, j = bj % NN;
    int hh = threadIdx.x;  // 256
    __shared__ float sw[NN];
    if (hh < NN) {
        if (lastLayer) {
            int len = clen[b] / TT;
            sw[hh] = (j == len) ? p[b * NN + hh] : 0.f;
        } else {
            sw[hh] = w[((size_t)(b * NN + hh)) * NN + j];
        }
    }
    __syncthreads();
    const float* pj = pmS + (size_t)bj * NW;
    float zj0 = pj[hh], zj1 = pj[HD + hh], zj2 = pj[2 * HD + hh], zj3 = pj[3 * HD + hh];
    float accC = 0.f, accH = 0.f, wsum = 0.f;
    for (int i = 0; i < NN; i++) {
        float wi = sw[i];
        wsum += wi;
        if (wi == 0.f) continue;
        int ri = b * NN + i;
        float cp, hp;
        if (j > i) {
            const float* ui = u + (size_t)ri * H4;
            float zi = zj0 + ui[hh];
            float zf = zj1 + ui[HD + hh];
            float zg = zj2 + ui[2 * HD + hh];
            float zo = zj3 + ui[3 * HD + hh];
            float cold = cIn[(size_t)ri * HD + hh];
            cp = sigw(zf) * cold + sigw(zi) * tanhw(zg);
            hp = sigw(zo) * tanhw(cp);
        } else {
            cp = cIn[(size_t)ri * HD + hh];
            hp = hIn[(size_t)ri * HD + hh];
        }
        accC += wi * cp;
        accH += wi * hp;
    }
    float inv = __fdividef(1.f, wsum + 1e-7f);
    cOut[(size_t)bj * HD + hh] = accC * inv;
    hOut[(size_t)bj * HD + hh] = accH * inv;
    if (hh == 0) pOut[bj] = wsum;
}

// ------------------------------------------------------------------------------
static float* sym(const void* s) {
    void* p = nullptr;
    cudaGetSymbolAddress(&p, s);
    return (float*)p;
}

extern "C" void kernel_launch(void* const* d_in, const int* in_sizes, int n_in,
                              void* d_out, int out_size) {
    const int*   ids    = (const int*)d_in[0];
    const int*   clen   = (const int*)d_in[1];
    const float* embed  = (const float*)d_in[2];
    const float* Wx_s   = (const float*)d_in[3];
    const float* Wh_s   = (const float*)d_in[4];
    const float* b_s    = (const float*)d_in[5];
    const float* W_se   = (const float*)d_in[6];
    const float* b_se   = (const float*)d_in[7];
    const float* Wx_e   = (const float*)d_in[8];
    const float* Wh_e   = (const float*)d_in[9];
    const float* b_e    = (const float*)d_in[10];
    const float* W_hk   = (const float*)d_in[11];
    const float* b_hk   = (const float*)d_in[12];
    const float* W_sd   = (const float*)d_in[13];
    const float* b_sd   = (const float*)d_in[14];
    const float* W_d1   = (const float*)d_in[15];
    const float* b_d1   = (const float*)d_in[16];
    const float* init_a = (const float*)d_in[17];
    const float* init_b = (const float*)d_in[18];

    float* xw    = sym(g_xw);
    float* Wt    = sym(g_Wt);
    float* Wxt   = sym(g_Wxt);
    float* bst   = sym(g_bst);
    float* B1    = sym(g_B1);
    float* B2    = sym(g_B2);
    float* c0    = sym(g_c0);
    float* hA    = sym(g_hA);
    float* hB    = sym(g_hB);
    float* pref  = sym(g_pref);
    float* MeMs  = sym(g_MeMs);
    float* pmS   = sym(g_pmS);
    float* be    = sym(g_be);
    float* bs    = sym(g_bs);
    float* uInit = sym(g_uInit);
    float* S2    = sym(g_S2);
    float* uBuf  = sym(g_u);
    float* hk    = sym(g_hk);
    float* wM    = sym(g_w);
    float* cX    = sym(g_cX);
    float* hX    = sym(g_hX);
    float* cY    = sym(g_cY);
    float* hY    = sym(g_hY);
    float* pX    = sym(g_pX);
    float* pY    = sym(g_pY);

    cudaFuncSetAttribute(lstm_persist_kernel,
                         cudaFuncAttributeMaxDynamicSharedMemorySize, LSTM_SMEM_BYTES);

    // 0) merged prep (also computes uInit, resets barrier)
    prep_kernel<<<(HD * NW + 255) / 256, 256>>>(
        Wh_s, Wx_s, b_s, Wh_e, W_hk, Wx_e, W_sd, b_se, b_e, b_sd, init_b,
        Wt, Wxt, bst, B1, B2, be, bs, uInit);

    // 1) token projection (gate-interleaved output)
    mma_gemm<0><<<dim3(TOK / 64, H4 / 64), 256>>>(
        embed, ids, Wxt, bst, xw, TOK, H4,
        nullptr, nullptr, nullptr, nullptr, nullptr, nullptr, nullptr);

    // 2) statement LSTM — persistent (final h lands in hB)
    lstm_persist_kernel<<<96, 256, LSTM_SMEM_BYTES>>>(xw, Wt, c0, hA, hB);

    // 3) prefix sums — two-level scan
    cumsum_kernel<<<BB, 1024>>>(hB, pref);

    // 4) composed tables
    mma_gemm<0><<<dim3(HD / 64, NW / 64), 256>>>(
        W_se, nullptr, B2, nullptr, MeMs, HD, NW,
        nullptr, nullptr, nullptr, nullptr, nullptr, nullptr, nullptr);
    mma_gemm<0><<<dim3((ROWS + 63) / 64, NW / 64), 256>>>(
        pref, nullptr, MeMs, nullptr, pmS, ROWS, NW,
        nullptr, nullptr, nullptr, nullptr, nullptr, nullptr, nullptr);

    // 5) S2 + layer-0 closed form (merged)
    s2_layer0_kernel<<<ROWS, 256>>>(pmS, bs, W_d1, S2, uInit, init_a, cX, hX, pX);

    // 6) layers 1..5
    float *cS = cX, *hS = hX, *pS = pX, *cD = cY, *hD2 = hY, *pD = pY;
    for (int layer = 1; layer < NLAY; layer++) {
        int last = (layer == NLAY - 1);
        // last layer: no softmax -> hk columns unneeded -> launch only u tiles
        int ytiles = last ? (H4 / 64) : (NW / 64);
        mma_gemm<2><<<dim3((ROWS + 63) / 64, ytiles), 256>>>(
            hS, nullptr, B1, nullptr, nullptr, ROWS, NW,
            be, pmS, b_hk, W_d1, uBuf, hk, pS);
        if (!last)
            softmax_kernel<<<ROWS, 256>>>(hk, S2, b_d1, pS, clen, layer, wM);
        float* hOutPtr = last ? (float*)d_out : hD2;
        agg_kernel<<<ROWS, 256>>>(wM, pmS, uBuf, cS, hS, cD, hOutPtr, pD,
                                  pS, clen, last);
        float* t;
        t = cS; cS = cD; cD = t;
        t = hS; hS = hD2; hD2 = t;
        t = pS; pS = pD; pD = t;
    }
}

// round 15
// speedup vs baseline: 1.0971x; 1.0210x over previous
#include <cuda_runtime.h>
#include <cstdio>
#include <cstdint>

#define BB 4
#define NSS 96
#define TT 8
#define HD 256
#define H4 1024
#define NW 1280
#define NN 97
#define NLAY 6
#define ROWS (BB*NN)     // 388
#define SEQS (BB*NSS)    // 384
#define TOK  (SEQS*TT)   // 3072

// ---------------- scratch -----------------------------------------------------
__device__ float g_xw[TOK*H4];         // token proj, GATE-INTERLEAVED [row][hh*4+g]
__device__ float g_Wt[HD*H4];          // Wh_s gate-interleaved [k][hh*4+g]
__device__ float g_Wxt[HD*H4];         // Wx_s gate-interleaved
__device__ float g_bst[H4];            // b_s gate-interleaved
__device__ float g_B2[HD*NW];          // [Wx_e | W_sd]
__device__ float g_c0[SEQS*HD];
__device__ float g_hA[SEQS*HD];
__device__ float g_hB[SEQS*HD];
__device__ float g_pref[ROWS*HD];
__device__ float g_MeMs[HD*NW];
__device__ float g_pmS[ROWS*NW];       // cols 0-1023 = pm4, 1024+ = prS
__device__ float g_be[H4];
__device__ float g_bs[HD];
__device__ float g_uInit[H4];          // init_b@Wh_e + b_se@Wx_e + b_e
__device__ float g_skipP[BB*NN*NN];    // layer-invariant softmax (layers 1..4)
__device__ float g_u[ROWS*H4];
__device__ float g_cX[ROWS*HD], g_hX[ROWS*HD];
__device__ float g_cY[ROWS*HD], g_hY[ROWS*HD];
__device__ float g_pX[ROWS], g_pY[ROWS];
__device__ unsigned g_barL;            // lstm grid-barrier counter

// exp-based gates (statement LSTM / layer0 path)
__device__ __forceinline__ float sigf(float x) {
    return __fdividef(1.0f, 1.0f + __expf(-x));
}
__device__ __forceinline__ float tanhr(float x) {
    return 2.0f * __fdividef(1.0f, 1.0f + __expf(-2.0f * x)) - 1.0f;
}
// HW-tanh gates (agg hot loop)
__device__ __forceinline__ float tanhw(float x) {
    float y;
    asm("tanh.approx.f32 %0, %1;" : "=f"(y) : "f"(x));
    return y;
}
__device__ __forceinline__ float sigw(float x) {
    return fmaf(0.5f, tanhw(0.5f * x), 0.5f);
}

__device__ __forceinline__ float to_tf32(float x) {
    uint32_t o;
    asm("cvt.rna.tf32.f32 %0, %1;" : "=r"(o) : "f"(x));
    return __uint_as_float(o);
}

__device__ __forceinline__ void mma_tf32(float& c0, float& c1, float& c2, float& c3,
                                         float a0, float a1, float a2, float a3,
                                         float b0, float b1) {
    asm volatile(
        "mma.sync.aligned.m16n8k8.row.col.f32.tf32.tf32.f32 "
        "{%0,%1,%2,%3},{%4,%5,%6,%7},{%8,%9},{%0,%1,%2,%3};"
        : "+f"(c0), "+f"(c1), "+f"(c2), "+f"(c3)
        : "r"(__float_as_uint(a0)), "r"(__float_as_uint(a1)),
          "r"(__float_as_uint(a2)), "r"(__float_as_uint(a3)),
          "r"(__float_as_uint(b0)), "r"(__float_as_uint(b1)));
}

// generation-based grid barrier
__device__ __forceinline__ void grid_bar(unsigned* ctr, unsigned* gen, unsigned nb) {
    __syncthreads();
    if (threadIdx.x == 0) {
        *gen += nb;
        unsigned target = *gen;
        __threadfence();
        atomicAdd(ctr, 1u);
        while (*(volatile unsigned*)ctr < target) __nanosleep(64);
        __threadfence();
    }
    __syncthreads();
}

// ---------------- tf32 MMA GEMM, K=256, tile 64x64, double-buffered -----------
// EPI: 0 = plain (+opt bias), 2 = u epilogue (v + be - pm4) with p-tile skip
#define SA_STRIDE 36
#define SB_STRIDE 72
#define BUF_STRIDE 68
#define TILE_FLOATS (64*SA_STRIDE + 32*SB_STRIDE)   // 4608
template<int EPI>
__global__ __launch_bounds__(256)
void mma_gemm(const float* __restrict__ A, const int* __restrict__ gidx,
              const float* __restrict__ B, const float* __restrict__ bias,
              float* __restrict__ C, int M, int N,
              const float* __restrict__ be, const float* __restrict__ pmS,
              float* __restrict__ u, const float* __restrict__ pcheck) {
    __shared__ float smem[2 * TILE_FLOATS];
    __shared__ int s_active;
    const int tid = threadIdx.x;
    const int lane = tid & 31, warp = tid >> 5;
    const int wm = warp >> 1, wn = warp & 1;
    const int g = lane >> 2, tg = lane & 3;
    const int bm = blockIdx.x * 64, bn = blockIdx.y * 64;

    if (EPI == 2) {
        if (tid == 0) s_active = 0;
        __syncthreads();
        if (tid < 64) {
            int row = bm + tid;
            if (row < M && pcheck[row] != 0.f) s_active = 1;
        }
        __syncthreads();
        if (!s_active) return;   // u rows stale; unread because p==0 downstream
    }

    const int ar_r  = tid >> 3;
    const int ar_kc = (tid & 7) << 2;
    const int br_kk = tid >> 4;
    const int br_c  = (tid & 15) << 2;

    float4 va[2], vb[2];
    auto load_regs = [&](int k0) {
#pragma unroll
        for (int l = 0; l < 2; l++) {
            int r = ar_r + l * 32;
            int row = bm + r;
            float4 v = make_float4(0.f, 0.f, 0.f, 0.f);
            if (row < M) {
                int ar = gidx ? gidx[row] : row;
                v = *(const float4*)(A + (size_t)ar * HD + k0 + ar_kc);
            }
            va[l] = v;
        }
#pragma unroll
        for (int l = 0; l < 2; l++) {
            int kk = br_kk + l * 16;
            vb[l] = *(const float4*)(B + (size_t)(k0 + kk) * N + bn + br_c);
        }
    };
    auto store_smem = [&](int buf) {
        float* sA = smem + buf * TILE_FLOATS;
        float* sB = sA + 64 * SA_STRIDE;
#pragma unroll
        for (int l = 0; l < 2; l++) {
            float* d = sA + (ar_r + l * 32) * SA_STRIDE + ar_kc;
            d[0] = to_tf32(va[l].x); d[1] = to_tf32(va[l].y);
            d[2] = to_tf32(va[l].z); d[3] = to_tf32(va[l].w);
        }
#pragma unroll
        for (int l = 0; l < 2; l++) {
            float* d = sB + (br_kk + l * 16) * SB_STRIDE + br_c;
            d[0] = to_tf32(vb[l].x); d[1] = to_tf32(vb[l].y);
            d[2] = to_tf32(vb[l].z); d[3] = to_tf32(vb[l].w);
        }
    };

    float acc[4][4];
#pragma unroll
    for (int a = 0; a < 4; a++)
#pragma unroll
        for (int b = 0; b < 4; b++) acc[a][b] = 0.f;

    load_regs(0);
    store_smem(0);
    __syncthreads();

    constexpr int NT = HD / 32;
#pragma unroll
    for (int it = 0; it < NT; it++) {
        if (it + 1 < NT) load_regs((it + 1) * 32);
        const float* sA = smem + (it & 1) * TILE_FLOATS;
        const float* sB = sA + 64 * SA_STRIDE;
#pragma unroll
        for (int k8 = 0; k8 < 4; k8++) {
            int kb = k8 * 8;
            float a0 = sA[(wm * 16 + g) * SA_STRIDE + kb + tg];
            float a1 = sA[(wm * 16 + g + 8) * SA_STRIDE + kb + tg];
            float a2 = sA[(wm * 16 + g) * SA_STRIDE + kb + tg + 4];
            float a3 = sA[(wm * 16 + g + 8) * SA_STRIDE + kb + tg + 4];
#pragma unroll
            for (int nt = 0; nt < 4; nt++) {
                int nc = wn * 32 + nt * 8 + g;
                float b0 = sB[(kb + tg) * SB_STRIDE + nc];
                float b1 = sB[(kb + tg + 4) * SB_STRIDE + nc];
                mma_tf32(acc[nt][0], acc[nt][1], acc[nt][2], acc[nt][3],
                         a0, a1, a2, a3, b0, b1);
            }
        }
        if (it + 1 < NT) {
            store_smem((it + 1) & 1);
            __syncthreads();
        }
    }

#pragma unroll
    for (int nt = 0; nt < 4; nt++)
#pragma unroll
        for (int e = 0; e < 4; e++) {
            int row = bm + wm * 16 + g + ((e >> 1) ? 8 : 0);
            int col = bn + wn * 32 + nt * 8 + tg * 2 + (e & 1);
            if (row >= M) continue;
            float v = acc[nt][e];
            if (EPI == 0) {
                C[(size_t)row * N + col] = v + (bias ? bias[col] : 0.f);
            } else {  // EPI == 2: u only (N == H4)
                u[(size_t)row * H4 + col] = v + be[col] - pmS[(size_t)row * NW + col];
            }
        }
}

// ---------------- persistent statement LSTM (grid = 96) -----------------------
#define LSTM_SMEM_BYTES (2 * 18432 * 4)
__global__ __launch_bounds__(256)
void lstm_persist_kernel(const float* __restrict__ xw, const float* __restrict__ Wt,
                         float* __restrict__ c0, float* __restrict__ hA,
                         float* __restrict__ hB) {
    extern __shared__ float dyn[];
    float* sW = dyn;
    float* sA = dyn + 18432;
    unsigned gen = 0;
    const int tid = threadIdx.x;
    const int lane = tid & 31, warp = tid >> 5;
    const int wm = warp >> 1, wn = warp & 1;
    const int g = lane >> 2, tg = lane & 3;
    const int bm = (blockIdx.x % 6) * 64;
    const int bn = (blockIdx.x / 6) * 64;
    const int ar_r = tid >> 3, ar_kc = (tid & 7) << 2;
    const int br_kk = tid >> 4, br_c = (tid & 15) << 2;

#pragma unroll
    for (int ch = 0; ch < 8; ch++) {
        int k0 = ch * 32;
        float* sWc = sW + ch * (32 * SB_STRIDE);
#pragma unroll
        for (int l = 0; l < 2; l++) {
            int kk = br_kk + l * 16;
            float4 v = *(const float4*)(Wt + (size_t)(k0 + kk) * H4 + bn + br_c);
            float* d = sWc + kk * SB_STRIDE + br_c;
            d[0] = to_tf32(v.x); d[1] = to_tf32(v.y);
            d[2] = to_tf32(v.z); d[3] = to_tf32(v.w);
        }
    }

#pragma unroll
    for (int l = 0; l < 4; l++) {
        int pi = tid + l * 256;
        int lr = pi & 63, lh = pi >> 6;
        int row = bm + lr, hh = (bn >> 2) + lh;
        float4 x4 = *(const float4*)(xw + (size_t)row * (TT * H4) + hh * 4);
        float c2 = sigf(x4.x) * tanhr(x4.z);
        size_t idx = (size_t)row * HD + hh;
        c0[idx] = c2;
        hA[idx] = sigf(x4.w) * tanhr(c2);
    }
    grid_bar(&g_barL, &gen, gridDim.x);

    const float* hs = hA;
    float* hd = hB;
    for (int t = 1; t < TT; t++) {
#pragma unroll
        for (int ch = 0; ch < 8; ch++) {
            int k0 = ch * 32;
            float* sAc = sA + ch * (64 * SA_STRIDE);
#pragma unroll
            for (int l = 0; l < 2; l++) {
                int r = ar_r + l * 32;
                float4 v = __ldcg((const float4*)(hs + (size_t)(bm + r) * HD + k0 + ar_kc));
                float* d = sAc + r * SA_STRIDE + ar_kc;
                d[0] = to_tf32(v.x); d[1] = to_tf32(v.y);
                d[2] = to_tf32(v.z); d[3] = to_tf32(v.w);
            }
        }
        __syncthreads();

        float acc[4][4];
#pragma unroll
        for (int a = 0; a < 4; a++)
#pragma unroll
            for (int b = 0; b < 4; b++) acc[a][b] = 0.f;
#pragma unroll
        for (int it = 0; it < 8; it++) {
            const float* sAc = sA + it * (64 * SA_STRIDE);
            const float* sWc = sW + it * (32 * SB_STRIDE);
#pragma unroll
            for (int k8 = 0; k8 < 4; k8++) {
                int kb = k8 * 8;
                float a0 = sAc[(wm * 16 + g) * SA_STRIDE + kb + tg];
                float a1 = sAc[(wm * 16 + g + 8) * SA_STRIDE + kb + tg];
                float a2 = sAc[(wm * 16 + g) * SA_STRIDE + kb + tg + 4];
                float a3 = sAc[(wm * 16 + g + 8) * SA_STRIDE + kb + tg + 4];
#pragma unroll
                for (int nt = 0; nt < 4; nt++) {
                    int nc = wn * 32 + nt * 8 + g;
                    float b0 = sWc[(kb + tg) * SB_STRIDE + nc];
                    float b1 = sWc[(kb + tg + 4) * SB_STRIDE + nc];
                    mma_tf32(acc[nt][0], acc[nt][1], acc[nt][2], acc[nt][3],
                             a0, a1, a2, a3, b0, b1);
                }
            }
        }
        __syncthreads();

        float* buf = sA;
#pragma unroll
        for (int nt = 0; nt < 4; nt++)
#pragma unroll
            for (int e = 0; e < 4; e++) {
                int lr = wm * 16 + g + ((e >> 1) ? 8 : 0);
                int lc = wn * 32 + nt * 8 + tg * 2 + (e & 1);
                buf[lr * BUF_STRIDE + lc] = acc[nt][e];
            }
        __syncthreads();
#pragma unroll
        for (int l = 0; l < 4; l++) {
            int pi = tid + l * 256;
            int lr = pi & 63, lh = pi >> 6;
            int row = bm + lr, hh = (bn >> 2) + lh;
            float4 z4 = *(const float4*)(buf + lr * BUF_STRIDE + lh * 4);
            float4 x4 = *(const float4*)(xw + (size_t)row * (TT * H4) + t * H4 + hh * 4);
            float zi = z4.x + x4.x;
            float zf = z4.y + x4.y;
            float zg = z4.z + x4.z;
            float zo = z4.w + x4.w;
            size_t idx = (size_t)row * HD + hh;
            float cp = c0[idx];
            float c2 = sigf(zf) * cp + sigf(zi) * tanhr(zg);
            c0[idx] = c2;
            hd[idx] = sigf(zo) * tanhr(c2);
        }
        grid_bar(&g_barL, &gen, gridDim.x);
        const float* tmp = hs; hs = hd; hd = (float*)tmp;
    }
}

// ---------------- merged prep ------------------------------------------------
__global__ void prep_kernel(const float* __restrict__ Wh_s, const float* __restrict__ Wx_s,
                            const float* __restrict__ b_s,
                            const float* __restrict__ Wh_e,
                            const float* __restrict__ Wx_e, const float* __restrict__ W_sd,
                            const float* __restrict__ b_se, const float* __restrict__ b_e,
                            const float* __restrict__ b_sd, const float* __restrict__ init_b,
                            float* __restrict__ Wt, float* __restrict__ Wxt,
                            float* __restrict__ bst, float* __restrict__ B2,
                            float* __restrict__ be, float* __restrict__ bs,
                            float* __restrict__ uInit) {
    int idx = blockIdx.x * 256 + threadIdx.x;
    if (idx == 0) g_barL = 0u;
    if (idx < HD * H4) {
        int k = idx / H4, col = idx % H4;
        int g = col / HD, hh = col % HD;
        Wt[(size_t)k * H4 + hh * 4 + g] = Wh_s[idx];
        Wxt[(size_t)k * H4 + hh * 4 + g] = Wx_s[idx];
    }
    if (idx < H4) {
        int g = idx / HD, hh = idx % HD;
        bst[hh * 4 + g] = b_s[idx];
    }
    if (idx < HD * NW) {
        int k = idx / NW, c = idx % NW;
        B2[idx] = (c < H4) ? Wx_e[(size_t)k * H4 + c] : W_sd[(size_t)k * HD + (c - H4)];
    }
    if (idx < H4) {
        float acc = b_e[idx];
        for (int k = 0; k < HD; k++) acc += b_se[k] * Wx_e[(size_t)k * H4 + idx];
        be[idx] = acc;
    } else if (idx < H4 + HD) {
        int c = idx - H4;
        float acc = b_sd[c];
        for (int k = 0; k < HD; k++) acc += b_se[k] * W_sd[(size_t)k * HD + c];
        bs[c] = acc;
    } else if (idx >= 2048 && idx < 2048 + H4) {
        int n = idx - 2048;   // uInit = init_b@Wh_e + b_se@Wx_e + b_e
        float acc = b_e[n];
        for (int k = 0; k < HD; k++) acc += init_b[k] * Wh_e[(size_t)k * H4 + n];
        for (int k = 0; k < HD; k++) acc += b_se[k] * Wx_e[(size_t)k * H4 + n];
        uInit[n] = acc;
    }
}

// ---------------- cumsum: two-level scan (4 blocks x 1024 threads) ------------
#define SEG_LEN (NSS / 4)   // 24
__global__ __launch_bounds__(1024)
void cumsum_kernel(const float* __restrict__ stmt, float* __restrict__ pref) {
    int b = blockIdx.x;
    int seg = threadIdx.x >> 8;
    int hh = threadIdx.x & 255;
    __shared__ float tot[4][256];

    float v[SEG_LEN];
    float run = 0.f;
#pragma unroll
    for (int l = 0; l < SEG_LEN; l++) {
        float x = stmt[(size_t)(b * NSS + seg * SEG_LEN + l) * HD + hh];
        run += x;
        v[l] = run;
    }
    tot[seg][hh] = run;
    __syncthreads();
    float off = 0.f;
#pragma unroll
    for (int s = 0; s < 4; s++)
        if (s < seg) off += tot[s][hh];

    if (seg == 0) pref[(size_t)(b * NN) * HD + hh] = 0.f;
#pragma unroll
    for (int l = 0; l < SEG_LEN; l++)
        pref[(size_t)(b * NN + seg * SEG_LEN + l + 1) * HD + hh] = off + v[l];
}

// ---------------- merged S2-row + layer-invariant softmax + layer-0 -----------
// Per block bi: compute S2 row in smem, masked softmax (middle-layer mask,
// h_key/b_d1 cancel) -> skipP; plus layer-0 closed form.
__global__ void s2_layer0_kernel(const float* __restrict__ pmS, const float* __restrict__ bs,
                                 const float* __restrict__ W_d1,
                                 const float* __restrict__ uInit,
                                 const float* __restrict__ init_a,
                                 const int* __restrict__ clen,
                                 float* __restrict__ skipP,
                                 float* __restrict__ cD, float* __restrict__ hD,
                                 float* __restrict__ pD) {
    int bi = blockIdx.x;
    int b = bi / NN, i = bi % NN;
    int tid = threadIdx.x;
    int lane = tid & 31, warp = tid >> 5;
    __shared__ float s2row[128];
    __shared__ float red[256];

    // --- layer 0 closed form ---
    int hh = tid;
    if (hh == 0) pD[bi] = (i == 1) ? 1.f : 0.f;
    size_t cidx = (size_t)bi * HD + hh;
    if (i != 1) {
        cD[cidx] = 0.f; hD[cidx] = 0.f;
    } else {
        const float* pj = pmS + (size_t)(b * NN + 1) * NW;
        float zi = pj[hh]          + uInit[hh];
        float zf = pj[HD + hh]     + uInit[HD + hh];
        float zg = pj[2 * HD + hh] + uInit[2 * HD + hh];
        float zo = pj[3 * HD + hh] + uInit[3 * HD + hh];
        float c2 = sigf(zf) * init_a[hh] + sigf(zi) * tanhr(zg);
        float h2 = sigf(zo) * tanhr(c2);
        float inv = __fdividef(1.f, 1.f + 1e-7f);
        cD[cidx] = c2 * inv;
        hD[cidx] = h2 * inv;
    }

    // --- S2 row into smem (8 warps stride j) ---
    const float* pi = pmS + (size_t)bi * NW + H4;
    for (int j = warp; j < NN; j += 8) {
        const float* pj = pmS + (size_t)(b * NN + j) * NW + H4;
        float acc = 0.f;
#pragma unroll
        for (int l = 0; l < 8; l++) {
            int h2 = lane + l * 32;
            float v = pj[h2] - pi[h2] + bs[h2];
            acc += fmaxf(v, 0.f) * W_d1[HD + h2];
        }
        for (int o = 16; o; o >>= 1) acc += __shfl_xor_sync(0xFFFFFFFFu, acc, o);
        if (lane == 0) s2row[j] = acc;
    }
    __syncthreads();

    // --- layer-invariant masked softmax over this row (mask of layers 1..4) ---
    int len = clen[b] / TT;
    int j = tid;
    bool m = (j < NN) && (((j > i) && (j <= len)) || (j == len));
    float logit = m ? s2row[j] : -1e30f;
    red[tid] = logit; __syncthreads();
    for (int s = 128; s > 0; s >>= 1) {
        if (tid < s) red[tid] = fmaxf(red[tid], red[tid + s]);
        __syncthreads();
    }
    float mx = red[0]; __syncthreads();
    float e = m ? __expf(logit - mx) : 0.f;
    red[tid] = e; __syncthreads();
    for (int s = 128; s > 0; s >>= 1) {
        if (tid < s) red[tid] += red[tid + s];
        __syncthreads();
    }
    float sum = red[0];
    if (j < NN) skipP[(size_t)bi * NN + j] = __fdividef(e, sum);
}

// ---------------- gated aggregation -------------------------------------------
// middle layers: w[i,j] = p[i] * skipP[i,j];  last: w[i][len] = p[i]
__global__ void agg_kernel(const float* __restrict__ skipP, const float* __restrict__ pmS,
                           const float* __restrict__ u,
                           const float* __restrict__ cIn, const float* __restrict__ hIn,
                           float* __restrict__ cOut, float* __restrict__ hOut,
                           float* __restrict__ pOut,
                           const float* __restrict__ p, const int* __restrict__ clen,
                           int lastLayer) {
    int bj = blockIdx.x, b = bj / NN, j = bj % NN;
    int hh = threadIdx.x;  // 256
    __shared__ float sw[NN];
    if (hh < NN) {
        float pv = p[b * NN + hh];
        if (lastLayer) {
            int len = clen[b] / TT;
            sw[hh] = (j == len) ? pv : 0.f;
        } else {
            sw[hh] = (pv == 0.f) ? 0.f
                   : pv * skipP[((size_t)(b * NN + hh)) * NN + j];
        }
    }
    __syncthreads();
    const float* pj = pmS + (size_t)bj * NW;
    float zj0 = pj[hh], zj1 = pj[HD + hh], zj2 = pj[2 * HD + hh], zj3 = pj[3 * HD + hh];
    float accC = 0.f, accH = 0.f, wsum = 0.f;
    for (int i = 0; i < NN; i++) {
        float wi = sw[i];
        wsum += wi;
        if (wi == 0.f) continue;
        int ri = b * NN + i;
        float cp, hp;
        if (j > i) {
            const float* ui = u + (size_t)ri * H4;
            float zi = zj0 + ui[hh];
            float zf = zj1 + ui[HD + hh];
            float zg = zj2 + ui[2 * HD + hh];
            float zo = zj3 + ui[3 * HD + hh];
            float cold = cIn[(size_t)ri * HD + hh];
            cp = sigw(zf) * cold + sigw(zi) * tanhw(zg);
            hp = sigw(zo) * tanhw(cp);
        } else {
            cp = cIn[(size_t)ri * HD + hh];
            hp = hIn[(size_t)ri * HD + hh];
        }
        accC += wi * cp;
        accH += wi * hp;
    }
    float inv = __fdividef(1.f, wsum + 1e-7f);
    cOut[(size_t)bj * HD + hh] = accC * inv;
    hOut[(size_t)bj * HD + hh] = accH * inv;
    if (hh == 0) pOut[bj] = wsum;
}

// ------------------------------------------------------------------------------
static float* sym(const void* s) {
    void* p = nullptr;
    cudaGetSymbolAddress(&p, s);
    return (float*)p;
}

extern "C" void kernel_launch(void* const* d_in, const int* in_sizes, int n_in,
                              void* d_out, int out_size) {
    const int*   ids    = (const int*)d_in[0];
    const int*   clen   = (const int*)d_in[1];
    const float* embed  = (const float*)d_in[2];
    const float* Wx_s   = (const float*)d_in[3];
    const float* Wh_s   = (const float*)d_in[4];
    const float* b_s    = (const float*)d_in[5];
    const float* W_se   = (const float*)d_in[6];
    const float* b_se   = (const float*)d_in[7];
    const float* Wx_e   = (const float*)d_in[8];
    const float* Wh_e   = (const float*)d_in[9];
    const float* b_e    = (const float*)d_in[10];
    const float* W_hk   = (const float*)d_in[11];
    const float* b_hk   = (const float*)d_in[12];
    const float* W_sd   = (const float*)d_in[13];
    const float* b_sd   = (const float*)d_in[14];
    const float* W_d1   = (const float*)d_in[15];
    const float* b_d1   = (const float*)d_in[16];
    const float* init_a = (const float*)d_in[17];
    const float* init_b = (const float*)d_in[18];
    (void)W_hk; (void)b_hk; (void)b_d1;   // cancel in the softmax (constant in j)

    float* xw    = sym(g_xw);
    float* Wt    = sym(g_Wt);
    float* Wxt   = sym(g_Wxt);
    float* bst   = sym(g_bst);
    float* B2    = sym(g_B2);
    float* c0    = sym(g_c0);
    float* hA    = sym(g_hA);
    float* hB    = sym(g_hB);
    float* pref  = sym(g_pref);
    float* MeMs  = sym(g_MeMs);
    float* pmS   = sym(g_pmS);
    float* be    = sym(g_be);
    float* bs    = sym(g_bs);
    float* uInit = sym(g_uInit);
    float* skipP = sym(g_skipP);
    float* uBuf  = sym(g_u);
    float* cX    = sym(g_cX);
    float* hX    = sym(g_hX);
    float* cY    = sym(g_cY);
    float* hY    = sym(g_hY);
    float* pX    = sym(g_pX);
    float* pY    = sym(g_pY);

    cudaFuncSetAttribute(lstm_persist_kernel,
                         cudaFuncAttributeMaxDynamicSharedMemorySize, LSTM_SMEM_BYTES);

    // 0) merged prep
    prep_kernel<<<(HD * NW + 255) / 256, 256>>>(
        Wh_s, Wx_s, b_s, Wh_e, Wx_e, W_sd, b_se, b_e, b_sd, init_b,
        Wt, Wxt, bst, B2, be, bs, uInit);

    // 1) token projection (gate-interleaved output)
    mma_gemm<0><<<dim3(TOK / 64, H4 / 64), 256>>>(
        embed, ids, Wxt, bst, xw, TOK, H4,
        nullptr, nullptr, nullptr, nullptr);

    // 2) statement LSTM — persistent (final h lands in hB)
    lstm_persist_kernel<<<96, 256, LSTM_SMEM_BYTES>>>(xw, Wt, c0, hA, hB);

    // 3) prefix sums — two-level scan
    cumsum_kernel<<<BB, 1024>>>(hB, pref);

    // 4) composed tables
    mma_gemm<0><<<dim3(HD / 64, NW / 64), 256>>>(
        W_se, nullptr, B2, nullptr, MeMs, HD, NW,
        nullptr, nullptr, nullptr, nullptr);
    mma_gemm<0><<<dim3((ROWS + 63) / 64, NW / 64), 256>>>(
        pref, nullptr, MeMs, nullptr, pmS, ROWS, NW,
        nullptr, nullptr, nullptr, nullptr);

    // 5) S2 + layer-invariant softmax + layer-0 closed form (merged)
    s2_layer0_kernel<<<ROWS, 256>>>(pmS, bs, W_d1, uInit, init_a, clen,
                                    skipP, cX, hX, pX);

    // 6) layers 1..5: GEMM(u) + agg only (softmax precomputed / degenerate)
    float *cS = cX, *hS = hX, *pS = pX, *cD = cY, *hD2 = hY, *pD = pY;
    for (int layer = 1; layer < NLAY; layer++) {
        int last = (layer == NLAY - 1);
        mma_gemm<2><<<dim3((ROWS + 63) / 64, H4 / 64), 256>>>(
            hS, nullptr, Wh_e, nullptr, nullptr, ROWS, H4,
            be, pmS, uBuf, pS);
        float* hOutPtr = last ? (float*)d_out : hD2;
        agg_kernel<<<ROWS, 256>>>(skipP, pmS, uBuf, cS, hS, cD, hOutPtr, pD,
                                  pS, clen, last);
        float* t;
        t = cS; cS = cD; cD = t;
        t = hS; hS = hD2; hD2 = t;
        t = pS; pS = pD; pD = t;
    }
}

// round 16
// speedup vs baseline: 1.1814x; 1.0768x over previous
#include <cuda_runtime.h>
#include <cstdio>
#include <cstdint>

#define BB 4
#define NSS 96
#define TT 8
#define HD 256
#define H4 1024
#define NW 1280
#define NN 97
#define NLAY 6
#define ROWS (BB*NN)     // 388
#define SEQS (BB*NSS)    // 384
#define TOK  (SEQS*TT)   // 3072

// ---------------- scratch -----------------------------------------------------
__device__ float g_xw[TOK*H4];         // token proj, GATE-INTERLEAVED [row][hh*4+g]
__device__ float g_Wt[HD*H4];          // Wh_s gate-interleaved [k][hh*4+g]
__device__ float g_Wxt[HD*H4];         // Wx_s gate-interleaved
__device__ float g_bst[H4];            // b_s gate-interleaved
__device__ float g_B2[HD*NW];          // [Wx_e | W_sd]
__device__ float g_c0[SEQS*HD];
__device__ float g_hA[SEQS*HD];
__device__ float g_hB[SEQS*HD];
__device__ float g_pref[ROWS*HD];
__device__ float g_segTot[16*HD];      // cumsum segment totals
__device__ float g_MeMs[HD*NW];
__device__ float g_pmS[ROWS*NW];       // cols 0-1023 = pm4, 1024+ = prS
__device__ float g_be[H4];
__device__ float g_bs[HD];
__device__ float g_uInit[H4];          // init_b@Wh_e + b_se@Wx_e + b_e
__device__ float g_skipP[BB*NN*NN];    // layer-invariant softmax (layers 1..4)
__device__ float g_u[ROWS*H4];
__device__ float g_cX[ROWS*HD], g_hX[ROWS*HD];
__device__ float g_cY[ROWS*HD], g_hY[ROWS*HD];
__device__ float g_pX[ROWS], g_pY[ROWS];
__device__ unsigned g_barL;            // lstm grid-barrier counter

// exp-based gates (statement LSTM / layer0 path)
__device__ __forceinline__ float sigf(float x) {
    return __fdividef(1.0f, 1.0f + __expf(-x));
}
__device__ __forceinline__ float tanhr(float x) {
    return 2.0f * __fdividef(1.0f, 1.0f + __expf(-2.0f * x)) - 1.0f;
}
// HW-tanh gates (agg hot loop)
__device__ __forceinline__ float tanhw(float x) {
    float y;
    asm("tanh.approx.f32 %0, %1;" : "=f"(y) : "f"(x));
    return y;
}
__device__ __forceinline__ float sigw(float x) {
    return fmaf(0.5f, tanhw(0.5f * x), 0.5f);
}

__device__ __forceinline__ float to_tf32(float x) {
    uint32_t o;
    asm("cvt.rna.tf32.f32 %0, %1;" : "=r"(o) : "f"(x));
    return __uint_as_float(o);
}

__device__ __forceinline__ void mma_tf32(float& c0, float& c1, float& c2, float& c3,
                                         float a0, float a1, float a2, float a3,
                                         float b0, float b1) {
    asm volatile(
        "mma.sync.aligned.m16n8k8.row.col.f32.tf32.tf32.f32 "
        "{%0,%1,%2,%3},{%4,%5,%6,%7},{%8,%9},{%0,%1,%2,%3};"
        : "+f"(c0), "+f"(c1), "+f"(c2), "+f"(c3)
        : "r"(__float_as_uint(a0)), "r"(__float_as_uint(a1)),
          "r"(__float_as_uint(a2)), "r"(__float_as_uint(a3)),
          "r"(__float_as_uint(b0)), "r"(__float_as_uint(b1)));
}

// generation-based grid barrier
__device__ __forceinline__ void grid_bar(unsigned* ctr, unsigned* gen, unsigned nb) {
    __syncthreads();
    if (threadIdx.x == 0) {
        *gen += nb;
        unsigned target = *gen;
        __threadfence();
        atomicAdd(ctr, 1u);
        while (*(volatile unsigned*)ctr < target) __nanosleep(64);
        __threadfence();
    }
    __syncthreads();
}

// ---------------- tf32 MMA GEMM, K=256, tile 64x64, double-buffered -----------
#define SA_STRIDE 36
#define SB_STRIDE 72
#define BUF_STRIDE 68
#define TILE_FLOATS (64*SA_STRIDE + 32*SB_STRIDE)   // 4608

// shared tile body (device-inlined). EPI 0 = plain+bias, 2 = u epilogue.
template<int EPI>
__device__ __forceinline__ void gemm_tile_body(
    float* smem, int bm, int bn,
    const float* __restrict__ A, const int* __restrict__ gidx,
    const float* __restrict__ B, const float* __restrict__ bias,
    float* __restrict__ C, int M, int N,
    const float* __restrict__ be, const float* __restrict__ pmS,
    float* __restrict__ u) {
    const int tid = threadIdx.x;
    const int lane = tid & 31, warp = tid >> 5;
    const int wm = warp >> 1, wn = warp & 1;
    const int g = lane >> 2, tg = lane & 3;
    const int ar_r  = tid >> 3;
    const int ar_kc = (tid & 7) << 2;
    const int br_kk = tid >> 4;
    const int br_c  = (tid & 15) << 2;

    float4 va[2], vb[2];
    auto load_regs = [&](int k0) {
#pragma unroll
        for (int l = 0; l < 2; l++) {
            int r = ar_r + l * 32;
            int row = bm + r;
            float4 v = make_float4(0.f, 0.f, 0.f, 0.f);
            if (row < M) {
                int ar = gidx ? gidx[row] : row;
                v = *(const float4*)(A + (size_t)ar * HD + k0 + ar_kc);
            }
            va[l] = v;
        }
#pragma unroll
        for (int l = 0; l < 2; l++) {
            int kk = br_kk + l * 16;
            vb[l] = *(const float4*)(B + (size_t)(k0 + kk) * N + bn + br_c);
        }
    };
    auto store_smem = [&](int buf) {
        float* sA = smem + buf * TILE_FLOATS;
        float* sB = sA + 64 * SA_STRIDE;
#pragma unroll
        for (int l = 0; l < 2; l++) {
            float* d = sA + (ar_r + l * 32) * SA_STRIDE + ar_kc;
            d[0] = to_tf32(va[l].x); d[1] = to_tf32(va[l].y);
            d[2] = to_tf32(va[l].z); d[3] = to_tf32(va[l].w);
        }
#pragma unroll
        for (int l = 0; l < 2; l++) {
            float* d = sB + (br_kk + l * 16) * SB_STRIDE + br_c;
            d[0] = to_tf32(vb[l].x); d[1] = to_tf32(vb[l].y);
            d[2] = to_tf32(vb[l].z); d[3] = to_tf32(vb[l].w);
        }
    };

    float acc[4][4];
#pragma unroll
    for (int a = 0; a < 4; a++)
#pragma unroll
        for (int b2 = 0; b2 < 4; b2++) acc[a][b2] = 0.f;

    load_regs(0);
    store_smem(0);
    __syncthreads();

    constexpr int NT = HD / 32;
#pragma unroll
    for (int it = 0; it < NT; it++) {
        if (it + 1 < NT) load_regs((it + 1) * 32);
        const float* sA = smem + (it & 1) * TILE_FLOATS;
        const float* sB = sA + 64 * SA_STRIDE;
#pragma unroll
        for (int k8 = 0; k8 < 4; k8++) {
            int kb = k8 * 8;
            float a0 = sA[(wm * 16 + g) * SA_STRIDE + kb + tg];
            float a1 = sA[(wm * 16 + g + 8) * SA_STRIDE + kb + tg];
            float a2 = sA[(wm * 16 + g) * SA_STRIDE + kb + tg + 4];
            float a3 = sA[(wm * 16 + g + 8) * SA_STRIDE + kb + tg + 4];
#pragma unroll
            for (int nt = 0; nt < 4; nt++) {
                int nc = wn * 32 + nt * 8 + g;
                float b0 = sB[(kb + tg) * SB_STRIDE + nc];
                float b1 = sB[(kb + tg + 4) * SB_STRIDE + nc];
                mma_tf32(acc[nt][0], acc[nt][1], acc[nt][2], acc[nt][3],
                         a0, a1, a2, a3, b0, b1);
            }
        }
        if (it + 1 < NT) {
            store_smem((it + 1) & 1);
            __syncthreads();
        }
    }

#pragma unroll
    for (int nt = 0; nt < 4; nt++)
#pragma unroll
        for (int e = 0; e < 4; e++) {
            int row = bm + wm * 16 + g + ((e >> 1) ? 8 : 0);
            int col = bn + wn * 32 + nt * 8 + tg * 2 + (e & 1);
            if (row >= M) continue;
            float v = acc[nt][e];
            if (EPI == 0) {
                C[(size_t)row * N + col] = v + (bias ? bias[col] : 0.f);
            } else {  // EPI == 2: u only (N == H4)
                u[(size_t)row * H4 + col] = v + be[col] - pmS[(size_t)row * NW + col];
            }
        }
}

// plain GEMM launcher (pmS table)
__global__ __launch_bounds__(256)
void mma_gemm0(const float* __restrict__ A, const float* __restrict__ B,
               float* __restrict__ C, int M, int N) {
    __shared__ float smem[2 * TILE_FLOATS];
    gemm_tile_body<0>(smem, blockIdx.x * 64, blockIdx.y * 64, A, nullptr, B, nullptr,
                      C, M, N, nullptr, nullptr, nullptr);
}

// dual-job GEMM: blocks [0,768) token projection; [768,848) MeMs
__global__ __launch_bounds__(256)
void gemm_dual(const float* __restrict__ embed, const int* __restrict__ ids,
               const float* __restrict__ Wxt, const float* __restrict__ bst,
               float* __restrict__ xw,
               const float* __restrict__ W_se, const float* __restrict__ B2,
               float* __restrict__ MeMs) {
    __shared__ float smem[2 * TILE_FLOATS];
    int bid = blockIdx.x;
    if (bid < 768) {
        int bm = (bid % 48) * 64, bn = (bid / 48) * 64;
        gemm_tile_body<0>(smem, bm, bn, embed, ids, Wxt, bst, xw, TOK, H4,
                          nullptr, nullptr, nullptr);
    } else {
        bid -= 768;
        int bm = (bid % 4) * 64, bn = (bid / 4) * 64;
        gemm_tile_body<0>(smem, bm, bn, W_se, nullptr, B2, nullptr, MeMs, HD, NW,
                          nullptr, nullptr, nullptr);
    }
}

// u GEMM with p-based tile skip
__global__ __launch_bounds__(256)
void mma_gemm_u(const float* __restrict__ A, const float* __restrict__ B,
                int M, const float* __restrict__ be, const float* __restrict__ pmS,
                float* __restrict__ u, const float* __restrict__ pcheck) {
    __shared__ float smem[2 * TILE_FLOATS];
    __shared__ int s_active;
    const int tid = threadIdx.x;
    const int bm = blockIdx.x * 64, bn = blockIdx.y * 64;
    if (tid == 0) s_active = 0;
    __syncthreads();
    if (tid < 64) {
        int row = bm + tid;
        if (row < M && pcheck[row] != 0.f) s_active = 1;
    }
    __syncthreads();
    if (!s_active) return;
    gemm_tile_body<2>(smem, bm, bn, A, nullptr, B, nullptr, nullptr, M, H4,
                      be, pmS, u);
}

// ---------------- persistent statement LSTM + fused cumsum (grid = 96) --------
#define LSTM_SMEM_BYTES (2 * 18432 * 4)
#define SEG_LEN (NSS / 4)   // 24
__global__ __launch_bounds__(256)
void lstm_persist_kernel(const float* __restrict__ xw, const float* __restrict__ Wt,
                         float* __restrict__ c0, float* __restrict__ hA,
                         float* __restrict__ hB,
                         float* __restrict__ pref, float* __restrict__ segTot) {
    extern __shared__ float dyn[];
    float* sW = dyn;
    float* sA = dyn + 18432;
    unsigned gen = 0;
    const int tid = threadIdx.x;
    const int lane = tid & 31, warp = tid >> 5;
    const int wm = warp >> 1, wn = warp & 1;
    const int g = lane >> 2, tg = lane & 3;
    const int bm = (blockIdx.x % 6) * 64;
    const int bn = (blockIdx.x / 6) * 64;
    const int ar_r = tid >> 3, ar_kc = (tid & 7) << 2;
    const int br_kk = tid >> 4, br_c = (tid & 15) << 2;

#pragma unroll
    for (int ch = 0; ch < 8; ch++) {
        int k0 = ch * 32;
        float* sWc = sW + ch * (32 * SB_STRIDE);
#pragma unroll
        for (int l = 0; l < 2; l++) {
            int kk = br_kk + l * 16;
            float4 v = *(const float4*)(Wt + (size_t)(k0 + kk) * H4 + bn + br_c);
            float* d = sWc + kk * SB_STRIDE + br_c;
            d[0] = to_tf32(v.x); d[1] = to_tf32(v.y);
            d[2] = to_tf32(v.z); d[3] = to_tf32(v.w);
        }
    }

#pragma unroll
    for (int l = 0; l < 4; l++) {
        int pi = tid + l * 256;
        int lr = pi & 63, lh = pi >> 6;
        int row = bm + lr, hh = (bn >> 2) + lh;
        float4 x4 = *(const float4*)(xw + (size_t)row * (TT * H4) + hh * 4);
        float c2 = sigf(x4.x) * tanhr(x4.z);
        size_t idx = (size_t)row * HD + hh;
        c0[idx] = c2;
        hA[idx] = sigf(x4.w) * tanhr(c2);
    }
    grid_bar(&g_barL, &gen, gridDim.x);

    const float* hs = hA;
    float* hd = hB;
    for (int t = 1; t < TT; t++) {
#pragma unroll
        for (int ch = 0; ch < 8; ch++) {
            int k0 = ch * 32;
            float* sAc = sA + ch * (64 * SA_STRIDE);
#pragma unroll
            for (int l = 0; l < 2; l++) {
                int r = ar_r + l * 32;
                float4 v = __ldcg((const float4*)(hs + (size_t)(bm + r) * HD + k0 + ar_kc));
                float* d = sAc + r * SA_STRIDE + ar_kc;
                d[0] = to_tf32(v.x); d[1] = to_tf32(v.y);
                d[2] = to_tf32(v.z); d[3] = to_tf32(v.w);
            }
        }
        __syncthreads();

        float acc[4][4];
#pragma unroll
        for (int a = 0; a < 4; a++)
#pragma unroll
            for (int b = 0; b < 4; b++) acc[a][b] = 0.f;
#pragma unroll
        for (int it = 0; it < 8; it++) {
            const float* sAc = sA + it * (64 * SA_STRIDE);
            const float* sWc = sW + it * (32 * SB_STRIDE);
#pragma unroll
            for (int k8 = 0; k8 < 4; k8++) {
                int kb = k8 * 8;
                float a0 = sAc[(wm * 16 + g) * SA_STRIDE + kb + tg];
                float a1 = sAc[(wm * 16 + g + 8) * SA_STRIDE + kb + tg];
                float a2 = sAc[(wm * 16 + g) * SA_STRIDE + kb + tg + 4];
                float a3 = sAc[(wm * 16 + g + 8) * SA_STRIDE + kb + tg + 4];
#pragma unroll
                for (int nt = 0; nt < 4; nt++) {
                    int nc = wn * 32 + nt * 8 + g;
                    float b0 = sWc[(kb + tg) * SB_STRIDE + nc];
                    float b1 = sWc[(kb + tg + 4) * SB_STRIDE + nc];
                    mma_tf32(acc[nt][0], acc[nt][1], acc[nt][2], acc[nt][3],
                             a0, a1, a2, a3, b0, b1);
                }
            }
        }
        __syncthreads();

        float* buf = sA;
#pragma unroll
        for (int nt = 0; nt < 4; nt++)
#pragma unroll
            for (int e = 0; e < 4; e++) {
                int lr = wm * 16 + g + ((e >> 1) ? 8 : 0);
                int lc = wn * 32 + nt * 8 + tg * 2 + (e & 1);
                buf[lr * BUF_STRIDE + lc] = acc[nt][e];
            }
        __syncthreads();
#pragma unroll
        for (int l = 0; l < 4; l++) {
            int pi = tid + l * 256;
            int lr = pi & 63, lh = pi >> 6;
            int row = bm + lr, hh = (bn >> 2) + lh;
            float4 z4 = *(const float4*)(buf + lr * BUF_STRIDE + lh * 4);
            float4 x4 = *(const float4*)(xw + (size_t)row * (TT * H4) + t * H4 + hh * 4);
            float zi = z4.x + x4.x;
            float zf = z4.y + x4.y;
            float zg = z4.z + x4.z;
            float zo = z4.w + x4.w;
            size_t idx = (size_t)row * HD + hh;
            float cp = c0[idx];
            float c2 = sigf(zf) * cp + sigf(zi) * tanhr(zg);
            c0[idx] = c2;
            hd[idx] = sigf(zo) * tanhr(c2);
        }
        grid_bar(&g_barL, &gen, gridDim.x);
        const float* tmp = hs; hs = hd; hd = (float*)tmp;
    }

    // ---- fused cumsum: blocks 0..15 do two-level scan over final h (= hs) ----
    float v[SEG_LEN];
    int b = blockIdx.x >> 2, seg = blockIdx.x & 3, hh = tid;
    if (blockIdx.x < 16) {
        float run = 0.f;
#pragma unroll
        for (int l = 0; l < SEG_LEN; l++) {
            run += __ldcg(hs + (size_t)(b * NSS + seg * SEG_LEN + l) * HD + hh);
            v[l] = run;
        }
        segTot[(size_t)(b * 4 + seg) * HD + hh] = run;
    }
    grid_bar(&g_barL, &gen, gridDim.x);
    if (blockIdx.x < 16) {
        float off = 0.f;
#pragma unroll
        for (int s = 0; s < 4; s++)
            if (s < seg) off += segTot[(size_t)(b * 4 + s) * HD + hh];
        if (seg == 0) pref[(size_t)(b * NN) * HD + hh] = 0.f;
#pragma unroll
        for (int l = 0; l < SEG_LEN; l++)
            pref[(size_t)(b * NN + seg * SEG_LEN + l + 1) * HD + hh] = off + v[l];
    }
}

// ---------------- merged prep ------------------------------------------------
__global__ void prep_kernel(const float* __restrict__ Wh_s, const float* __restrict__ Wx_s,
                            const float* __restrict__ b_s,
                            const float* __restrict__ Wh_e,
                            const float* __restrict__ Wx_e, const float* __restrict__ W_sd,
                            const float* __restrict__ b_se, const float* __restrict__ b_e,
                            const float* __restrict__ b_sd, const float* __restrict__ init_b,
                            float* __restrict__ Wt, float* __restrict__ Wxt,
                            float* __restrict__ bst, float* __restrict__ B2,
                            float* __restrict__ be, float* __restrict__ bs,
                            float* __restrict__ uInit) {
    int idx = blockIdx.x * 256 + threadIdx.x;
    if (idx == 0) g_barL = 0u;
    if (idx < HD * H4) {
        int k = idx / H4, col = idx % H4;
        int g = col / HD, hh = col % HD;
        Wt[(size_t)k * H4 + hh * 4 + g] = Wh_s[idx];
        Wxt[(size_t)k * H4 + hh * 4 + g] = Wx_s[idx];
    }
    if (idx < H4) {
        int g = idx / HD, hh = idx % HD;
        bst[hh * 4 + g] = b_s[idx];
    }
    if (idx < HD * NW) {
        int k = idx / NW, c = idx % NW;
        B2[idx] = (c < H4) ? Wx_e[(size_t)k * H4 + c] : W_sd[(size_t)k * HD + (c - H4)];
    }
    if (idx < H4) {
        float acc = b_e[idx];
        for (int k = 0; k < HD; k++) acc += b_se[k] * Wx_e[(size_t)k * H4 + idx];
        be[idx] = acc;
    } else if (idx < H4 + HD) {
        int c = idx - H4;
        float acc = b_sd[c];
        for (int k = 0; k < HD; k++) acc += b_se[k] * W_sd[(size_t)k * HD + c];
        bs[c] = acc;
    } else if (idx >= 2048 && idx < 2048 + H4) {
        int n = idx - 2048;   // uInit = init_b@Wh_e + b_se@Wx_e + b_e
        float acc = b_e[n];
        for (int k = 0; k < HD; k++) acc += init_b[k] * Wh_e[(size_t)k * H4 + n];
        for (int k = 0; k < HD; k++) acc += b_se[k] * Wx_e[(size_t)k * H4 + n];
        uInit[n] = acc;
    }
}

// ---------------- merged S2-row + layer-invariant softmax + layer-0 -----------
__global__ void s2_layer0_kernel(const float* __restrict__ pmS, const float* __restrict__ bs,
                                 const float* __restrict__ W_d1,
                                 const float* __restrict__ uInit,
                                 const float* __restrict__ init_a,
                                 const int* __restrict__ clen,
                                 float* __restrict__ skipP,
                                 float* __restrict__ cD, float* __restrict__ hD,
                                 float* __restrict__ pD) {
    int bi = blockIdx.x;
    int b = bi / NN, i = bi % NN;
    int tid = threadIdx.x;
    int lane = tid & 31, warp = tid >> 5;
    __shared__ float s2row[128];
    __shared__ float red[256];

    // --- layer 0 closed form ---
    int hh = tid;
    if (hh == 0) pD[bi] = (i == 1) ? 1.f : 0.f;
    size_t cidx = (size_t)bi * HD + hh;
    if (i != 1) {
        cD[cidx] = 0.f; hD[cidx] = 0.f;
    } else {
        const float* pj = pmS + (size_t)(b * NN + 1) * NW;
        float zi = pj[hh]          + uInit[hh];
        float zf = pj[HD + hh]     + uInit[HD + hh];
        float zg = pj[2 * HD + hh] + uInit[2 * HD + hh];
        float zo = pj[3 * HD + hh] + uInit[3 * HD + hh];
        float c2 = sigf(zf) * init_a[hh] + sigf(zi) * tanhr(zg);
        float h2 = sigf(zo) * tanhr(c2);
        float inv = __fdividef(1.f, 1.f + 1e-7f);
        cD[cidx] = c2 * inv;
        hD[cidx] = h2 * inv;
    }

    // --- S2 row into smem (8 warps stride j) ---
    const float* pi = pmS + (size_t)bi * NW + H4;
    for (int j = warp; j < NN; j += 8) {
        const float* pj = pmS + (size_t)(b * NN + j) * NW + H4;
        float acc = 0.f;
#pragma unroll
        for (int l = 0; l < 8; l++) {
            int h2 = lane + l * 32;
            float v = pj[h2] - pi[h2] + bs[h2];
            acc += fmaxf(v, 0.f) * W_d1[HD + h2];
        }
        for (int o = 16; o; o >>= 1) acc += __shfl_xor_sync(0xFFFFFFFFu, acc, o);
        if (lane == 0) s2row[j] = acc;
    }
    __syncthreads();

    // --- layer-invariant masked softmax (middle-layer mask; h_key cancels) ---
    int len = clen[b] / TT;
    int j = tid;
    bool m = (j < NN) && (((j > i) && (j <= len)) || (j == len));
    float logit = m ? s2row[j] : -1e30f;
    red[tid] = logit; __syncthreads();
    for (int s = 128; s > 0; s >>= 1) {
        if (tid < s) red[tid] = fmaxf(red[tid], red[tid + s]);
        __syncthreads();
    }
    float mx = red[0]; __syncthreads();
    float e = m ? __expf(logit - mx) : 0.f;
    red[tid] = e; __syncthreads();
    for (int s = 128; s > 0; s >>= 1) {
        if (tid < s) red[tid] += red[tid + s];
        __syncthreads();
    }
    float sum = red[0];
    if (j < NN) skipP[(size_t)bi * NN + j] = __fdividef(e, sum);
}

// ---------------- gated aggregation -------------------------------------------
__global__ void agg_kernel(const float* __restrict__ skipP, const float* __restrict__ pmS,
                           const float* __restrict__ u,
                           const float* __restrict__ cIn, const float* __restrict__ hIn,
                           float* __restrict__ cOut, float* __restrict__ hOut,
                           float* __restrict__ pOut,
                           const float* __restrict__ p, const int* __restrict__ clen,
                           int lastLayer) {
    int bj = blockIdx.x, b = bj / NN, j = bj % NN;
    int hh = threadIdx.x;  // 256
    __shared__ float sw[NN];
    if (hh < NN) {
        float pv = p[b * NN + hh];
        if (lastLayer) {
            int len = clen[b] / TT;
            sw[hh] = (j == len) ? pv : 0.f;
        } else {
            sw[hh] = (pv == 0.f) ? 0.f
                   : pv * skipP[((size_t)(b * NN + hh)) * NN + j];
        }
    }
    __syncthreads();
    const float* pj = pmS + (size_t)bj * NW;
    float zj0 = pj[hh], zj1 = pj[HD + hh], zj2 = pj[2 * HD + hh], zj3 = pj[3 * HD + hh];
    float accC = 0.f, accH = 0.f, wsum = 0.f;
    for (int i = 0; i < NN; i++) {
        float wi = sw[i];
        wsum += wi;
        if (wi == 0.f) continue;
        int ri = b * NN + i;
        float cp, hp;
        if (j > i) {
            const float* ui = u + (size_t)ri * H4;
            float zi = zj0 + ui[hh];
            float zf = zj1 + ui[HD + hh];
            float zg = zj2 + ui[2 * HD + hh];
            float zo = zj3 + ui[3 * HD + hh];
            float cold = cIn[(size_t)ri * HD + hh];
            cp = sigw(zf) * cold + sigw(zi) * tanhw(zg);
            hp = sigw(zo) * tanhw(cp);
        } else {
            cp = cIn[(size_t)ri * HD + hh];
            hp = hIn[(size_t)ri * HD + hh];
        }
        accC += wi * cp;
        accH += wi * hp;
    }
    float inv = __fdividef(1.f, wsum + 1e-7f);
    cOut[(size_t)bj * HD + hh] = accC * inv;
    hOut[(size_t)bj * HD + hh] = accH * inv;
    if (hh == 0) pOut[bj] = wsum;
}

// ------------------------------------------------------------------------------
static float* sym(const void* s) {
    void* p = nullptr;
    cudaGetSymbolAddress(&p, s);
    return (float*)p;
}

extern "C" void kernel_launch(void* const* d_in, const int* in_sizes, int n_in,
                              void* d_out, int out_size) {
    const int*   ids    = (const int*)d_in[0];
    const int*   clen   = (const int*)d_in[1];
    const float* embed  = (const float*)d_in[2];
    const float* Wx_s   = (const float*)d_in[3];
    const float* Wh_s   = (const float*)d_in[4];
    const float* b_s    = (const float*)d_in[5];
    const float* W_se   = (const float*)d_in[6];
    const float* b_se   = (const float*)d_in[7];
    const float* Wx_e   = (const float*)d_in[8];
    const float* Wh_e   = (const float*)d_in[9];
    const float* b_e    = (const float*)d_in[10];
    const float* W_hk   = (const float*)d_in[11];
    const float* b_hk   = (const float*)d_in[12];
    const float* W_sd   = (const float*)d_in[13];
    const float* b_sd   = (const float*)d_in[14];
    const float* W_d1   = (const float*)d_in[15];
    const float* b_d1   = (const float*)d_in[16];
    const float* init_a = (const float*)d_in[17];
    const float* init_b = (const float*)d_in[18];
    (void)W_hk; (void)b_hk; (void)b_d1;   // cancel in the softmax (constant in j)

    float* xw    = sym(g_xw);
    float* Wt    = sym(g_Wt);
    float* Wxt   = sym(g_Wxt);
    float* bst   = sym(g_bst);
    float* B2    = sym(g_B2);
    float* c0    = sym(g_c0);
    float* hA    = sym(g_hA);
    float* hB    = sym(g_hB);
    float* pref  = sym(g_pref);
    float* segT  = sym(g_segTot);
    float* MeMs  = sym(g_MeMs);
    float* pmS   = sym(g_pmS);
    float* be    = sym(g_be);
    float* bs    = sym(g_bs);
    float* uInit = sym(g_uInit);
    float* skipP = sym(g_skipP);
    float* uBuf  = sym(g_u);
    float* cX    = sym(g_cX);
    float* hX    = sym(g_hX);
    float* cY    = sym(g_cY);
    float* hY    = sym(g_hY);
    float* pX    = sym(g_pX);
    float* pY    = sym(g_pY);

    cudaFuncSetAttribute(lstm_persist_kernel,
                         cudaFuncAttributeMaxDynamicSharedMemorySize, LSTM_SMEM_BYTES);

    // 0) merged prep
    prep_kernel<<<(HD * NW + 255) / 256, 256>>>(
        Wh_s, Wx_s, b_s, Wh_e, Wx_e, W_sd, b_se, b_e, b_sd, init_b,
        Wt, Wxt, bst, B2, be, bs, uInit);

    // 1) token projection + MeMs table in ONE launch (independent jobs)
    gemm_dual<<<848, 256>>>(embed, ids, Wxt, bst, xw, W_se, B2, MeMs);

    // 2) statement LSTM — persistent, with fused prefix-sum tail
    lstm_persist_kernel<<<96, 256, LSTM_SMEM_BYTES>>>(xw, Wt, c0, hA, hB, pref, segT);

    // 3) pmS table
    mma_gemm0<<<dim3((ROWS + 63) / 64, NW / 64), 256>>>(pref, MeMs, pmS, ROWS, NW);

    // 4) S2 + layer-invariant softmax + layer-0 closed form (merged)
    s2_layer0_kernel<<<ROWS, 256>>>(pmS, bs, W_d1, uInit, init_a, clen,
                                    skipP, cX, hX, pX);

    // 5) layers 1..5: GEMM(u) + agg only
    float *cS = cX, *hS = hX, *pS = pX, *cD = cY, *hD2 = hY, *pD = pY;
    for (int layer = 1; layer < NLAY; layer++) {
        int last = (layer == NLAY - 1);
        mma_gemm_u<<<dim3((ROWS + 63) / 64, H4 / 64), 256>>>(
            hS, Wh_e, ROWS, be, pmS, uBuf, pS);
        float* hOutPtr = last ? (float*)d_out : hD2;
        agg_kernel<<<ROWS, 256>>>(skipP, pmS, uBuf, cS, hS, cD, hOutPtr, pD,
                                  pS, clen, last);
        float* t;
        t = cS; cS = cD; cD = t;
        t = hS; hS = hD2; hD2 = t;
        t = pS; pS = pD; pD = t;
    }
}

// round 17
// speedup vs baseline: 1.2213x; 1.0338x over previous
#include <cuda_runtime.h>
#include <cstdio>
#include <cstdint>

#define BB 4
#define NSS 96
#define TT 8
#define HD 256
#define H4 1024
#define NW 1280
#define NN 97
#define NLAY 6
#define ROWS (BB*NN)     // 388
#define SEQS (BB*NSS)    // 384
#define TOK  (SEQS*TT)   // 3072

// ---------------- scratch -----------------------------------------------------
__device__ float g_xw[TOK*H4];
__device__ float g_Wt[HD*H4];
__device__ float g_Wxt[HD*H4];
__device__ float g_bst[H4];
__device__ float g_B2[HD*NW];
__device__ float g_c0[SEQS*HD];
__device__ float g_hA[SEQS*HD];
__device__ float g_hB[SEQS*HD];
__device__ float g_pref[ROWS*HD];
__device__ float g_segTot[16*HD];
__device__ float g_MeMs[HD*NW];
__device__ float g_pmS[ROWS*NW];
__device__ float g_be[H4];
__device__ float g_bs[HD];
__device__ float g_uInit[H4];
__device__ float g_skipP[BB*NN*NN];
__device__ float g_u[ROWS*H4];
__device__ float g_cX[ROWS*HD], g_hX[ROWS*HD];
__device__ float g_cY[ROWS*HD], g_hY[ROWS*HD];
__device__ float g_pX[ROWS], g_pY[ROWS];
__device__ unsigned g_barL;

__device__ __forceinline__ float sigf(float x) {
    return __fdividef(1.0f, 1.0f + __expf(-x));
}
__device__ __forceinline__ float tanhr(float x) {
    return 2.0f * __fdividef(1.0f, 1.0f + __expf(-2.0f * x)) - 1.0f;
}
__device__ __forceinline__ float tanhw(float x) {
    float y;
    asm("tanh.approx.f32 %0, %1;" : "=f"(y) : "f"(x));
    return y;
}
__device__ __forceinline__ float sigw(float x) {
    return fmaf(0.5f, tanhw(0.5f * x), 0.5f);
}

__device__ __forceinline__ float to_tf32(float x) {
    uint32_t o;
    asm("cvt.rna.tf32.f32 %0, %1;" : "=r"(o) : "f"(x));
    return __uint_as_float(o);
}

__device__ __forceinline__ void mma_tf32(float& c0, float& c1, float& c2, float& c3,
                                         float a0, float a1, float a2, float a3,
                                         float b0, float b1) {
    asm volatile(
        "mma.sync.aligned.m16n8k8.row.col.f32.tf32.tf32.f32 "
        "{%0,%1,%2,%3},{%4,%5,%6,%7},{%8,%9},{%0,%1,%2,%3};"
        : "+f"(c0), "+f"(c1), "+f"(c2), "+f"(c3)
        : "r"(__float_as_uint(a0)), "r"(__float_as_uint(a1)),
          "r"(__float_as_uint(a2)), "r"(__float_as_uint(a3)),
          "r"(__float_as_uint(b0)), "r"(__float_as_uint(b1)));
}

__device__ __forceinline__ void grid_bar(unsigned* ctr, unsigned* gen, unsigned nb) {
    __syncthreads();
    if (threadIdx.x == 0) {
        *gen += nb;
        unsigned target = *gen;
        __threadfence();
        atomicAdd(ctr, 1u);
        while (*(volatile unsigned*)ctr < target) __nanosleep(64);
        __threadfence();
    }
    __syncthreads();
}

// ---------------- tf32 MMA GEMM, K=256, tile 64x64, double-buffered -----------
#define SA_STRIDE 36
#define SB_STRIDE 72
#define BUF_STRIDE 68
#define TILE_FLOATS (64*SA_STRIDE + 32*SB_STRIDE)   // 4608

template<int EPI>
__device__ __forceinline__ void gemm_tile_body(
    float* smem, int bm, int bn,
    const float* __restrict__ A, const int* __restrict__ gidx,
    const float* __restrict__ B, const float* __restrict__ bias,
    float* __restrict__ C, int M, int N,
    const float* __restrict__ be, const float* __restrict__ pmS,
    float* __restrict__ u) {
    const int tid = threadIdx.x;
    const int lane = tid & 31, warp = tid >> 5;
    const int wm = warp >> 1, wn = warp & 1;
    const int g = lane >> 2, tg = lane & 3;
    const int ar_r  = tid >> 3;
    const int ar_kc = (tid & 7) << 2;
    const int br_kk = tid >> 4;
    const int br_c  = (tid & 15) << 2;

    float4 va[2], vb[2];
    auto load_regs = [&](int k0) {
#pragma unroll
        for (int l = 0; l < 2; l++) {
            int r = ar_r + l * 32;
            int row = bm + r;
            float4 v = make_float4(0.f, 0.f, 0.f, 0.f);
            if (row < M) {
                int ar = gidx ? gidx[row] : row;
                v = *(const float4*)(A + (size_t)ar * HD + k0 + ar_kc);
            }
            va[l] = v;
        }
#pragma unroll
        for (int l = 0; l < 2; l++) {
            int kk = br_kk + l * 16;
            vb[l] = *(const float4*)(B + (size_t)(k0 + kk) * N + bn + br_c);
        }
    };
    auto store_smem = [&](int buf) {
        float* sA = smem + buf * TILE_FLOATS;
        float* sB = sA + 64 * SA_STRIDE;
#pragma unroll
        for (int l = 0; l < 2; l++) {
            float* d = sA + (ar_r + l * 32) * SA_STRIDE + ar_kc;
            d[0] = to_tf32(va[l].x); d[1] = to_tf32(va[l].y);
            d[2] = to_tf32(va[l].z); d[3] = to_tf32(va[l].w);
        }
#pragma unroll
        for (int l = 0; l < 2; l++) {
            float* d = sB + (br_kk + l * 16) * SB_STRIDE + br_c;
            d[0] = to_tf32(vb[l].x); d[1] = to_tf32(vb[l].y);
            d[2] = to_tf32(vb[l].z); d[3] = to_tf32(vb[l].w);
        }
    };

    float acc[4][4];
#pragma unroll
    for (int a = 0; a < 4; a++)
#pragma unroll
        for (int b2 = 0; b2 < 4; b2++) acc[a][b2] = 0.f;

    load_regs(0);
    store_smem(0);
    __syncthreads();

    constexpr int NT = HD / 32;
#pragma unroll
    for (int it = 0; it < NT; it++) {
        if (it + 1 < NT) load_regs((it + 1) * 32);
        const float* sA = smem + (it & 1) * TILE_FLOATS;
        const float* sB = sA + 64 * SA_STRIDE;
#pragma unroll
        for (int k8 = 0; k8 < 4; k8++) {
            int kb = k8 * 8;
            float a0 = sA[(wm * 16 + g) * SA_STRIDE + kb + tg];
            float a1 = sA[(wm * 16 + g + 8) * SA_STRIDE + kb + tg];
            float a2 = sA[(wm * 16 + g) * SA_STRIDE + kb + tg + 4];
            float a3 = sA[(wm * 16 + g + 8) * SA_STRIDE + kb + tg + 4];
#pragma unroll
            for (int nt = 0; nt < 4; nt++) {
                int nc = wn * 32 + nt * 8 + g;
                float b0 = sB[(kb + tg) * SB_STRIDE + nc];
                float b1 = sB[(kb + tg + 4) * SB_STRIDE + nc];
                mma_tf32(acc[nt][0], acc[nt][1], acc[nt][2], acc[nt][3],
                         a0, a1, a2, a3, b0, b1);
            }
        }
        if (it + 1 < NT) {
            store_smem((it + 1) & 1);
            __syncthreads();
        }
    }

#pragma unroll
    for (int nt = 0; nt < 4; nt++)
#pragma unroll
        for (int e = 0; e < 4; e++) {
            int row = bm + wm * 16 + g + ((e >> 1) ? 8 : 0);
            int col = bn + wn * 32 + nt * 8 + tg * 2 + (e & 1);
            if (row >= M) continue;
            float v = acc[nt][e];
            if (EPI == 0) {
                C[(size_t)row * N + col] = v + (bias ? bias[col] : 0.f);
            } else {  // EPI == 2: u only (N == H4)
                u[(size_t)row * H4 + col] = v + be[col] - pmS[(size_t)row * NW + col];
            }
        }
}

__global__ __launch_bounds__(256)
void mma_gemm0(const float* __restrict__ A, const float* __restrict__ B,
               float* __restrict__ C, int M, int N) {
    __shared__ float smem[2 * TILE_FLOATS];
    gemm_tile_body<0>(smem, blockIdx.x * 64, blockIdx.y * 64, A, nullptr, B, nullptr,
                      C, M, N, nullptr, nullptr, nullptr);
}

__global__ __launch_bounds__(256)
void gemm_dual(const float* __restrict__ embed, const int* __restrict__ ids,
               const float* __restrict__ Wxt, const float* __restrict__ bst,
               float* __restrict__ xw,
               const float* __restrict__ W_se, const float* __restrict__ B2,
               float* __restrict__ MeMs) {
    __shared__ float smem[2 * TILE_FLOATS];
    int bid = blockIdx.x;
    if (bid < 768) {
        int bm = (bid % 48) * 64, bn = (bid / 48) * 64;
        gemm_tile_body<0>(smem, bm, bn, embed, ids, Wxt, bst, xw, TOK, H4,
                          nullptr, nullptr, nullptr);
    } else {
        bid -= 768;
        int bm = (bid % 4) * 64, bn = (bid / 4) * 64;
        gemm_tile_body<0>(smem, bm, bn, W_se, nullptr, B2, nullptr, MeMs, HD, NW,
                          nullptr, nullptr, nullptr);
    }
}

__global__ __launch_bounds__(256)
void mma_gemm_u(const float* __restrict__ A, const float* __restrict__ B,
                int M, const float* __restrict__ be, const float* __restrict__ pmS,
                float* __restrict__ u, const float* __restrict__ pcheck) {
    __shared__ float smem[2 * TILE_FLOATS];
    __shared__ int s_active;
    const int tid = threadIdx.x;
    const int bm = blockIdx.x * 64, bn = blockIdx.y * 64;
    if (tid == 0) s_active = 0;
    __syncthreads();
    if (tid < 64) {
        int row = bm + tid;
        if (row < M && pcheck[row] != 0.f) s_active = 1;
    }
    __syncthreads();
    if (!s_active) return;
    gemm_tile_body<2>(smem, bm, bn, A, nullptr, B, nullptr, nullptr, M, H4,
                      be, pmS, u);
}

// ---------------- persistent statement LSTM + fused cumsum (grid = 96) --------
#define LSTM_SMEM_BYTES (2 * 18432 * 4)
#define SEG_LEN (NSS / 4)   // 24
__global__ __launch_bounds__(256)
void lstm_persist_kernel(const float* __restrict__ xw, const float* __restrict__ Wt,
                         float* __restrict__ c0, float* __restrict__ hA,
                         float* __restrict__ hB,
                         float* __restrict__ pref, float* __restrict__ segTot) {
    extern __shared__ float dyn[];
    float* sW = dyn;
    float* sA = dyn + 18432;
    unsigned gen = 0;
    const int tid = threadIdx.x;
    const int lane = tid & 31, warp = tid >> 5;
    const int wm = warp >> 1, wn = warp & 1;
    const int g = lane >> 2, tg = lane & 3;
    const int bm = (blockIdx.x % 6) * 64;
    const int bn = (blockIdx.x / 6) * 64;
    const int ar_r = tid >> 3, ar_kc = (tid & 7) << 2;
    const int br_kk = tid >> 4, br_c = (tid & 15) << 2;

#pragma unroll
    for (int ch = 0; ch < 8; ch++) {
        int k0 = ch * 32;
        float* sWc = sW + ch * (32 * SB_STRIDE);
#pragma unroll
        for (int l = 0; l < 2; l++) {
            int kk = br_kk + l * 16;
            float4 v = *(const float4*)(Wt + (size_t)(k0 + kk) * H4 + bn + br_c);
            float* d = sWc + kk * SB_STRIDE + br_c;
            d[0] = to_tf32(v.x); d[1] = to_tf32(v.y);
            d[2] = to_tf32(v.z); d[3] = to_tf32(v.w);
        }
    }

#pragma unroll
    for (int l = 0; l < 4; l++) {
        int pi = tid + l * 256;
        int lr = pi & 63, lh = pi >> 6;
        int row = bm + lr, hh = (bn >> 2) + lh;
        float4 x4 = *(const float4*)(xw + (size_t)row * (TT * H4) + hh * 4);
        float c2 = sigf(x4.x) * tanhr(x4.z);
        size_t idx = (size_t)row * HD + hh;
        c0[idx] = c2;
        hA[idx] = sigf(x4.w) * tanhr(c2);
    }
    grid_bar(&g_barL, &gen, gridDim.x);

    const float* hs = hA;
    float* hd = hB;
    for (int t = 1; t < TT; t++) {
#pragma unroll
        for (int ch = 0; ch < 8; ch++) {
            int k0 = ch * 32;
            float* sAc = sA + ch * (64 * SA_STRIDE);
#pragma unroll
            for (int l = 0; l < 2; l++) {
                int r = ar_r + l * 32;
                float4 v = __ldcg((const float4*)(hs + (size_t)(bm + r) * HD + k0 + ar_kc));
                float* d = sAc + r * SA_STRIDE + ar_kc;
                d[0] = to_tf32(v.x); d[1] = to_tf32(v.y);
                d[2] = to_tf32(v.z); d[3] = to_tf32(v.w);
            }
        }
        __syncthreads();

        float acc[4][4];
#pragma unroll
        for (int a = 0; a < 4; a++)
#pragma unroll
            for (int b = 0; b < 4; b++) acc[a][b] = 0.f;
#pragma unroll
        for (int it = 0; it < 8; it++) {
            const float* sAc = sA + it * (64 * SA_STRIDE);
            const float* sWc = sW + it * (32 * SB_STRIDE);
#pragma unroll
            for (int k8 = 0; k8 < 4; k8++) {
                int kb = k8 * 8;
                float a0 = sAc[(wm * 16 + g) * SA_STRIDE + kb + tg];
                float a1 = sAc[(wm * 16 + g + 8) * SA_STRIDE + kb + tg];
                float a2 = sAc[(wm * 16 + g) * SA_STRIDE + kb + tg + 4];
                float a3 = sAc[(wm * 16 + g + 8) * SA_STRIDE + kb + tg + 4];
#pragma unroll
                for (int nt = 0; nt < 4; nt++) {
                    int nc = wn * 32 + nt * 8 + g;
                    float b0 = sWc[(kb + tg) * SB_STRIDE + nc];
                    float b1 = sWc[(kb + tg + 4) * SB_STRIDE + nc];
                    mma_tf32(acc[nt][0], acc[nt][1], acc[nt][2], acc[nt][3],
                             a0, a1, a2, a3, b0, b1);
                }
            }
        }
        __syncthreads();

        float* buf = sA;
#pragma unroll
        for (int nt = 0; nt < 4; nt++)
#pragma unroll
            for (int e = 0; e < 4; e++) {
                int lr = wm * 16 + g + ((e >> 1) ? 8 : 0);
                int lc = wn * 32 + nt * 8 + tg * 2 + (e & 1);
                buf[lr * BUF_STRIDE + lc] = acc[nt][e];
            }
        __syncthreads();
#pragma unroll
        for (int l = 0; l < 4; l++) {
            int pi = tid + l * 256;
            int lr = pi & 63, lh = pi >> 6;
            int row = bm + lr, hh = (bn >> 2) + lh;
            float4 z4 = *(const float4*)(buf + lr * BUF_STRIDE + lh * 4);
            float4 x4 = *(const float4*)(xw + (size_t)row * (TT * H4) + t * H4 + hh * 4);
            float zi = z4.x + x4.x;
            float zf = z4.y + x4.y;
            float zg = z4.z + x4.z;
            float zo = z4.w + x4.w;
            size_t idx = (size_t)row * HD + hh;
            float cp = c0[idx];
            float c2 = sigf(zf) * cp + sigf(zi) * tanhr(zg);
            c0[idx] = c2;
            hd[idx] = sigf(zo) * tanhr(c2);
        }
        grid_bar(&g_barL, &gen, gridDim.x);
        const float* tmp = hs; hs = hd; hd = (float*)tmp;
    }

    // ---- fused cumsum tail (blocks 0..15) ----
    float v[SEG_LEN];
    int b = blockIdx.x >> 2, seg = blockIdx.x & 3, hh = tid;
    if (blockIdx.x < 16) {
        float run = 0.f;
#pragma unroll
        for (int l = 0; l < SEG_LEN; l++) {
            run += __ldcg(hs + (size_t)(b * NSS + seg * SEG_LEN + l) * HD + hh);
            v[l] = run;
        }
        segTot[(size_t)(b * 4 + seg) * HD + hh] = run;
    }
    grid_bar(&g_barL, &gen, gridDim.x);
    if (blockIdx.x < 16) {
        float off = 0.f;
#pragma unroll
        for (int s = 0; s < 4; s++)
            if (s < seg) off += segTot[(size_t)(b * 4 + s) * HD + hh];
        if (seg == 0) pref[(size_t)(b * NN) * HD + hh] = 0.f;
#pragma unroll
        for (int l = 0; l < SEG_LEN; l++)
            pref[(size_t)(b * NN + seg * SEG_LEN + l + 1) * HD + hh] = off + v[l];
    }
}

// ---------------- merged prep ------------------------------------------------
__global__ void prep_kernel(const float* __restrict__ Wh_s, const float* __restrict__ Wx_s,
                            const float* __restrict__ b_s,
                            const float* __restrict__ Wh_e,
                            const float* __restrict__ Wx_e, const float* __restrict__ W_sd,
                            const float* __restrict__ b_se, const float* __restrict__ b_e,
                            const float* __restrict__ b_sd, const float* __restrict__ init_b,
                            float* __restrict__ Wt, float* __restrict__ Wxt,
                            float* __restrict__ bst, float* __restrict__ B2,
                            float* __restrict__ be, float* __restrict__ bs,
                            float* __restrict__ uInit) {
    int idx = blockIdx.x * 256 + threadIdx.x;
    if (idx == 0) g_barL = 0u;
    if (idx < HD * H4) {
        int k = idx / H4, col = idx % H4;
        int g = col / HD, hh = col % HD;
        Wt[(size_t)k * H4 + hh * 4 + g] = Wh_s[idx];
        Wxt[(size_t)k * H4 + hh * 4 + g] = Wx_s[idx];
    }
    if (idx < H4) {
        int g = idx / HD, hh = idx % HD;
        bst[hh * 4 + g] = b_s[idx];
    }
    if (idx < HD * NW) {
        int k = idx / NW, c = idx % NW;
        B2[idx] = (c < H4) ? Wx_e[(size_t)k * H4 + c] : W_sd[(size_t)k * HD + (c - H4)];
    }
    if (idx < H4) {
        float acc = b_e[idx];
        for (int k = 0; k < HD; k++) acc += b_se[k] * Wx_e[(size_t)k * H4 + idx];
        be[idx] = acc;
    } else if (idx < H4 + HD) {
        int c = idx - H4;
        float acc = b_sd[c];
        for (int k = 0; k < HD; k++) acc += b_se[k] * W_sd[(size_t)k * HD + c];
        bs[c] = acc;
    } else if (idx >= 2048 && idx < 2048 + H4) {
        int n = idx - 2048;
        float acc = b_e[n];
        for (int k = 0; k < HD; k++) acc += init_b[k] * Wh_e[(size_t)k * H4 + n];
        for (int k = 0; k < HD; k++) acc += b_se[k] * Wx_e[(size_t)k * H4 + n];
        uInit[n] = acc;
    }
}

// ---------------- merged S2-row + layer-invariant softmax + layer-0 -----------
__global__ void s2_layer0_kernel(const float* __restrict__ pmS, const float* __restrict__ bs,
                                 const float* __restrict__ W_d1,
                                 const float* __restrict__ uInit,
                                 const float* __restrict__ init_a,
                                 const int* __restrict__ clen,
                                 float* __restrict__ skipP,
                                 float* __restrict__ cD, float* __restrict__ hD,
                                 float* __restrict__ pD) {
    int bi = blockIdx.x;
    int b = bi / NN, i = bi % NN;
    int tid = threadIdx.x;
    int lane = tid & 31, warp = tid >> 5;
    __shared__ float s2row[128];
    __shared__ float red[256];

    int hh = tid;
    if (hh == 0) pD[bi] = (i == 1) ? 1.f : 0.f;
    size_t cidx = (size_t)bi * HD + hh;
    if (i != 1) {
        cD[cidx] = 0.f; hD[cidx] = 0.f;
    } else {
        const float* pj = pmS + (size_t)(b * NN + 1) * NW;
        float zi = pj[hh]          + uInit[hh];
        float zf = pj[HD + hh]     + uInit[HD + hh];
        float zg = pj[2 * HD + hh] + uInit[2 * HD + hh];
        float zo = pj[3 * HD + hh] + uInit[3 * HD + hh];
        float c2 = sigf(zf) * init_a[hh] + sigf(zi) * tanhr(zg);
        float h2 = sigf(zo) * tanhr(c2);
        float inv = __fdividef(1.f, 1.f + 1e-7f);
        cD[cidx] = c2 * inv;
        hD[cidx] = h2 * inv;
    }

    const float* pi = pmS + (size_t)bi * NW + H4;
    for (int j = warp; j < NN; j += 8) {
        const float* pj = pmS + (size_t)(b * NN + j) * NW + H4;
        float acc = 0.f;
#pragma unroll
        for (int l = 0; l < 8; l++) {
            int h2 = lane + l * 32;
            float v = pj[h2] - pi[h2] + bs[h2];
            acc += fmaxf(v, 0.f) * W_d1[HD + h2];
        }
        for (int o = 16; o; o >>= 1) acc += __shfl_xor_sync(0xFFFFFFFFu, acc, o);
        if (lane == 0) s2row[j] = acc;
    }
    __syncthreads();

    int len = clen[b] / TT;
    int j = tid;
    bool m = (j < NN) && (((j > i) && (j <= len)) || (j == len));
    float logit = m ? s2row[j] : -1e30f;
    red[tid] = logit; __syncthreads();
    for (int s = 128; s > 0; s >>= 1) {
        if (tid < s) red[tid] = fmaxf(red[tid], red[tid + s]);
        __syncthreads();
    }
    float mx = red[0]; __syncthreads();
    float e = m ? __expf(logit - mx) : 0.f;
    red[tid] = e; __syncthreads();
    for (int s = 128; s > 0; s >>= 1) {
        if (tid < s) red[tid] += red[tid + s];
        __syncthreads();
    }
    float sum = red[0];
    if (j < NN) skipP[(size_t)bi * NN + j] = __fdividef(e, sum);
}

// ---------------- gated aggregation: 2 j-columns per block, compacted i-list --
// grid = BB*49*2 blocks, 128 threads. blk -> b, jp (j0=2jp, j1=j0+1), half.
__global__ __launch_bounds__(128)
void agg_kernel(const float* __restrict__ skipP, const float* __restrict__ pmS,
                const float* __restrict__ u,
                const float* __restrict__ cIn, const float* __restrict__ hIn,
                float* __restrict__ cOut, float* __restrict__ hOut,
                float* __restrict__ pOut,
                const float* __restrict__ p, const int* __restrict__ clen,
                int lastLayer) {
    int blk = blockIdx.x;
    int b = blk / 98;
    int rem = blk % 98;
    int jp = rem >> 1, half = rem & 1;
    int j0 = jp * 2, j1 = j0 + 1;
    bool has1 = (j1 < NN);
    int tid = threadIdx.x;          // 0..127
    int hh = half * 128 + tid;      // h-dim element
    int len = clen[b] / TT;

    __shared__ float sw0[NN], sw1[NN];
    __shared__ int actList[NN];
    __shared__ int warpOff[4];
    __shared__ int sNum;

    if (tid < NN) {
        float pv = p[b * NN + tid];
        if (lastLayer) {
            sw0[tid] = (j0 == len) ? pv : 0.f;
            sw1[tid] = (has1 && j1 == len) ? pv : 0.f;
        } else {
            if (pv == 0.f) { sw0[tid] = 0.f; sw1[tid] = 0.f; }
            else {
                sw0[tid] = pv * skipP[((size_t)(b * NN + tid)) * NN + j0];
                sw1[tid] = has1 ? pv * skipP[((size_t)(b * NN + tid)) * NN + j1] : 0.f;
            }
        }
    }
    __syncthreads();

    // deterministic compaction (order preserved by i)
    bool flag = (tid < NN) && (sw0[tid] != 0.f || sw1[tid] != 0.f);
    unsigned mball = __ballot_sync(0xFFFFFFFFu, flag);
    int lane = tid & 31, wrp = tid >> 5;
    int pos = __popc(mball & ((1u << lane) - 1u));
    if (lane == 0) warpOff[wrp] = __popc(mball);
    __syncthreads();
    if (tid == 0) {
        int s = 0;
#pragma unroll
        for (int w2 = 0; w2 < 4; w2++) { int t = warpOff[w2]; warpOff[w2] = s; s += t; }
        sNum = s;
    }
    __syncthreads();
    if (flag) actList[warpOff[wrp] + pos] = tid;
    __syncthreads();
    int nAct = sNum;

    const float* pj0 = pmS + (size_t)(b * NN + j0) * NW;
    float a00 = pj0[hh], a01 = pj0[HD + hh], a02 = pj0[2 * HD + hh], a03 = pj0[3 * HD + hh];
    float a10 = 0.f, a11 = 0.f, a12 = 0.f, a13 = 0.f;
    if (has1) {
        const float* pj1 = pmS + (size_t)(b * NN + j1) * NW;
        a10 = pj1[hh]; a11 = pj1[HD + hh]; a12 = pj1[2 * HD + hh]; a13 = pj1[3 * HD + hh];
    }

    float accC0 = 0.f, accH0 = 0.f, accC1 = 0.f, accH1 = 0.f;
    float wsum0 = 0.f, wsum1 = 0.f;
    for (int k = 0; k < nAct; k++) {
        int i = actList[k];
        float wi0 = sw0[i], wi1 = sw1[i];
        wsum0 += wi0; wsum1 += wi1;
        int ri = b * NN + i;
        float cold = cIn[(size_t)ri * HD + hh];
        int jmax = has1 ? j1 : j0;
        float u0 = 0.f, u1 = 0.f, u2 = 0.f, u3 = 0.f;
        if (jmax > i) {
            const float* ui = u + (size_t)ri * H4;
            u0 = ui[hh]; u1 = ui[HD + hh]; u2 = ui[2 * HD + hh]; u3 = ui[3 * HD + hh];
        }
        float hold = 0.f;
        if (j0 <= i) hold = hIn[(size_t)ri * HD + hh];
        if (wi0 != 0.f) {
            float cp, hp;
            if (j0 > i) {
                cp = sigw(a01 + u1) * cold + sigw(a00 + u0) * tanhw(a02 + u2);
                hp = sigw(a03 + u3) * tanhw(cp);
            } else { cp = cold; hp = hold; }
            accC0 += wi0 * cp; accH0 += wi0 * hp;
        }
        if (wi1 != 0.f) {
            float cp, hp;
            if (j1 > i) {
                cp = sigw(a11 + u1) * cold + sigw(a10 + u0) * tanhw(a12 + u2);
                hp = sigw(a13 + u3) * tanhw(cp);
            } else { cp = cold; hp = hold; }
            accC1 += wi1 * cp; accH1 += wi1 * hp;
        }
    }

    size_t o0 = (size_t)(b * NN + j0) * HD + hh;
    float inv0 = __fdividef(1.f, wsum0 + 1e-7f);
    cOut[o0] = accC0 * inv0;
    hOut[o0] = accH0 * inv0;
    if (tid == 0 && half == 0) pOut[b * NN + j0] = wsum0;
    if (has1) {
        size_t o1 = (size_t)(b * NN + j1) * HD + hh;
        float inv1 = __fdividef(1.f, wsum1 + 1e-7f);
        cOut[o1] = accC1 * inv1;
        hOut[o1] = accH1 * inv1;
        if (tid == 0 && half == 0) pOut[b * NN + j1] = wsum1;
    }
}

// ------------------------------------------------------------------------------
static float* sym(const void* s) {
    void* p = nullptr;
    cudaGetSymbolAddress(&p, s);
    return (float*)p;
}

extern "C" void kernel_launch(void* const* d_in, const int* in_sizes, int n_in,
                              void* d_out, int out_size) {
    const int*   ids    = (const int*)d_in[0];
    const int*   clen   = (const int*)d_in[1];
    const float* embed  = (const float*)d_in[2];
    const float* Wx_s   = (const float*)d_in[3];
    const float* Wh_s   = (const float*)d_in[4];
    const float* b_s    = (const float*)d_in[5];
    const float* W_se   = (const float*)d_in[6];
    const float* b_se   = (const float*)d_in[7];
    const float* Wx_e   = (const float*)d_in[8];
    const float* Wh_e   = (const float*)d_in[9];
    const float* b_e    = (const float*)d_in[10];
    const float* W_hk   = (const float*)d_in[11];
    const float* b_hk   = (const float*)d_in[12];
    const float* W_sd   = (const float*)d_in[13];
    const float* b_sd   = (const float*)d_in[14];
    const float* W_d1   = (const float*)d_in[15];
    const float* b_d1   = (const float*)d_in[16];
    const float* init_a = (const float*)d_in[17];
    const float* init_b = (const float*)d_in[18];
    (void)W_hk; (void)b_hk; (void)b_d1;

    float* xw    = sym(g_xw);
    float* Wt    = sym(g_Wt);
    float* Wxt   = sym(g_Wxt);
    float* bst   = sym(g_bst);
    float* B2    = sym(g_B2);
    float* c0    = sym(g_c0);
    float* hA    = sym(g_hA);
    float* hB    = sym(g_hB);
    float* pref  = sym(g_pref);
    float* segT  = sym(g_segTot);
    float* MeMs  = sym(g_MeMs);
    float* pmS   = sym(g_pmS);
    float* be    = sym(g_be);
    float* bs    = sym(g_bs);
    float* uInit = sym(g_uInit);
    float* skipP = sym(g_skipP);
    float* uBuf  = sym(g_u);
    float* cX    = sym(g_cX);
    float* hX    = sym(g_hX);
    float* cY    = sym(g_cY);
    float* hY    = sym(g_hY);
    float* pX    = sym(g_pX);
    float* pY    = sym(g_pY);

    cudaFuncSetAttribute(lstm_persist_kernel,
                         cudaFuncAttributeMaxDynamicSharedMemorySize, LSTM_SMEM_BYTES);

    // 0) merged prep
    prep_kernel<<<(HD * NW + 255) / 256, 256>>>(
        Wh_s, Wx_s, b_s, Wh_e, Wx_e, W_sd, b_se, b_e, b_sd, init_b,
        Wt, Wxt, bst, B2, be, bs, uInit);

    // 1) token projection + MeMs table in ONE launch
    gemm_dual<<<848, 256>>>(embed, ids, Wxt, bst, xw, W_se, B2, MeMs);

    // 2) statement LSTM — persistent, with fused prefix-sum tail
    lstm_persist_kernel<<<96, 256, LSTM_SMEM_BYTES>>>(xw, Wt, c0, hA, hB, pref, segT);

    // 3) pmS table
    mma_gemm0<<<dim3((ROWS + 63) / 64, NW / 64), 256>>>(pref, MeMs, pmS, ROWS, NW);

    // 4) S2 + layer-invariant softmax + layer-0 closed form
    s2_layer0_kernel<<<ROWS, 256>>>(pmS, bs, W_d1, uInit, init_a, clen,
                                    skipP, cX, hX, pX);

    // 5) layers 1..5: GEMM(u) + agg only
    float *cS = cX, *hS = hX, *pS = pX, *cD = cY, *hD2 = hY, *pD = pY;
    for (int layer = 1; layer < NLAY; layer++) {
        int last = (layer == NLAY - 1);
        mma_gemm_u<<<dim3((ROWS + 63) / 64, H4 / 64), 256>>>(
            hS, Wh_e, ROWS, be, pmS, uBuf, pS);
        float* hOutPtr = last ? (float*)d_out : hD2;
        agg_kernel<<<BB * 49 * 2, 128>>>(skipP, pmS, uBuf, cS, hS, cD, hOutPtr, pD,
                                         pS, clen, last);
        float* t;
        t = cS; cS = cD; cD = t;
        t = hS; hS = hD2; hD2 = t;
        t = pS; pS = pD; pD = t;
    }
}